// round 15
// baseline (speedup 1.0000x reference)
#include <cuda_runtime.h>
#include <cuda_bf16.h>
#include <cooperative_groups.h>

namespace cg = cooperative_groups;
typedef unsigned long long u64;

// ---------------------------------------------------------------------------
// PointNet++ encoder, B=2, N=16384, 4 SA stages (stride 4, nsample 32)
// ---------------------------------------------------------------------------

// ---------------- scratch buffers (device globals; no allocs allowed) ------
// Internal buffers use FIXED per-batch half strides (bhalf) so the two batch
// pipelines can be at different stages concurrently without overlap.
__device__ float g_P[4194304];     // projected feats P   half = 2097152
__device__ float g_h1[16777216];   // layer-1 out         half = 8388608
__device__ float g_h2[16777216];   // layer-2 out         half = 8388608
__device__ float g_fA[1048576];    // pooled feats ping   half = 524288
__device__ float g_fB[1048576];    // pooled feats pong   half = 524288
__device__ float g_feats0[98304];  // xyz^T               half = 49152
__device__ float g_q0[24576];      // stage0 query xyz    half = 12288
__device__ float g_q1[6144];       // stage1 query xyz    half = 3072
__device__ float g_q2[1536];       // stage2 query xyz    half = 768
__device__ float g_q3[384];        // stage3 query xyz    half = 192

__device__ __forceinline__ const float* fbufc(int code, const float* ext) {
    switch (code) {
        case 0: return g_P;   case 1: return g_h1;  case 2: return g_h2;
        case 3: return g_fA;  case 4: return g_fB;  case 5: return g_feats0;
        case 6: return g_q0;  case 7: return g_q1;  case 8: return g_q2;
        case 9: return g_q3;  default: return ext;
    }
}
__device__ __forceinline__ float* fbufw(int code, float* ext) {
    switch (code) {
        case 0: return g_P;   case 1: return g_h1;  case 2: return g_h2;
        case 3: return g_fA;  case 4: return g_fB;  case 5: return g_feats0;
        case 6: return g_q0;  case 7: return g_q1;  case 8: return g_q2;
        case 9: return g_q3;  default: return ext;
    }
}
__device__ __forceinline__ size_t bhalf(int code) {
    switch (code) {
        case 0: return 2097152u;  case 1: return 8388608u; case 2: return 8388608u;
        case 3: return 524288u;   case 4: return 524288u;  case 5: return 49152u;
        case 6: return 12288u;    case 7: return 3072u;    case 8: return 768u;
        case 9: return 192u;      default: return 0u;
    }
}

// d2 exactly as JAX computes it: ((dx*dx + dy*dy) + dz*dz), no FMA contraction
__device__ __forceinline__ float d2_exact(float dx, float dy, float dz) {
    return __fadd_rn(__fadd_rn(__fmul_rn(dx, dx), __fmul_rn(dy, dy)),
                     __fmul_rn(dz, dz));
}

// ---- packed f32x2 helpers (rn mul/add: per-lane bit-identical to scalar) ---
__device__ __forceinline__ u64 pack2(float lo, float hi) {
    u64 r; asm("mov.b64 %0,{%1,%2};" : "=l"(r) : "f"(lo), "f"(hi)); return r;
}
__device__ __forceinline__ void unpack2(u64 v, float& lo, float& hi) {
    asm("mov.b64 {%0,%1},%2;" : "=f"(lo), "=f"(hi) : "l"(v));
}
__device__ __forceinline__ u64 add2(u64 a, u64 b) {
    u64 r; asm("add.rn.f32x2 %0,%1,%2;" : "=l"(r) : "l"(a), "l"(b)); return r;
}
__device__ __forceinline__ u64 mul2(u64 a, u64 b) {
    u64 r; asm("mul.rn.f32x2 %0,%1,%2;" : "=l"(r) : "l"(a), "l"(b)); return r;
}

// ---------------- feats0 = xyz^T  [B,3,N] -----------------------------------
__global__ void k_transpose(const float* __restrict__ xyz) {
    int i = blockIdx.x * blockDim.x + threadIdx.x;
    if (i >= 2 * 16384) return;
    int b = i >> 14, n = i & 16383;
#pragma unroll
    for (int c = 0; c < 3; ++c)
        g_feats0[b * 49152 + c * 16384 + n] = xyz[(size_t)i * 3 + c];
}

// ---------------- FPS stage 0: 8-CTA cluster per batch (N=16384) ------------
struct __align__(16) SlotA { u64 key; float x, y; };

__global__ __cluster_dims__(8, 1, 1) __launch_bounds__(512, 1)
void k_fps_cl(const float* __restrict__ xyz, int N, int npoint) {
    cg::cluster_group cluster = cg::this_cluster();
    const int rank = cluster.block_rank();
    const int b = blockIdx.x >> 3;
    const int tid = threadIdx.x;
    const int gbase = rank * (N >> 3);        // 2048 pts per CTA

    __shared__ unsigned s_whi[16], s_wlo[16];
    __shared__ float s_wx[16], s_wy[16], s_wz[16];
    __shared__ SlotA s_sa[2][8];              // [parity][src rank]
    __shared__ float s_sz[2][8];
    __shared__ __align__(8) u64 s_mbar;

    const float* base = xyz + (size_t)b * N * 3;

    u64 px01, px23, py01, py23, pz01, pz23;
    float pxs[4], pys[4], pzs[4], md[4];
    {
#pragma unroll
        for (int j = 0; j < 4; ++j) {
            const float* p = base + (size_t)(gbase + tid + j * 512) * 3;
            pxs[j] = p[0]; pys[j] = p[1]; pzs[j] = p[2];
            md[j] = 1e10f;
        }
        px01 = pack2(pxs[0], pxs[1]); px23 = pack2(pxs[2], pxs[3]);
        py01 = pack2(pys[0], pys[1]); py23 = pack2(pys[2], pys[3]);
        pz01 = pack2(pzs[0], pzs[1]); pz23 = pack2(pzs[2], pzs[3]);
    }

    unsigned mbar32 = (unsigned)__cvta_generic_to_shared(&s_mbar);
    if (tid == 0)
        asm volatile("mbarrier.init.shared.b64 [%0], %1;"
                     :: "r"(mbar32), "r"(8) : "memory");

    float* qb = g_q0 + (size_t)b * 12288;
    float lx = base[0], ly = base[1], lz = base[2];
    if (rank == 0 && tid == 0) { qb[0] = lx; qb[1] = ly; qb[2] = lz; }
    cluster.sync();                            // mbarriers + slots live

    int par = 0;
    unsigned phase = 0;
    for (int it = 1; it < npoint; ++it) {
        u64 nlx2 = pack2(-lx, -lx), nly2 = pack2(-ly, -ly), nlz2 = pack2(-lz, -lz);
        float d0, d1, d2, d3;
        {
            u64 dx = add2(px01, nlx2), dy = add2(py01, nly2), dz = add2(pz01, nlz2);
            u64 s = add2(add2(mul2(dx, dx), mul2(dy, dy)), mul2(dz, dz));
            unpack2(s, d0, d1);
        }
        {
            u64 dx = add2(px23, nlx2), dy = add2(py23, nly2), dz = add2(pz23, nlz2);
            u64 s = add2(add2(mul2(dx, dx), mul2(dy, dy)), mul2(dz, dz));
            unpack2(s, d2, d3);
        }
        float m, bm; int bj;
        m = fminf(md[0], d0); md[0] = m; bm = m; bj = 0;
        m = fminf(md[1], d1); md[1] = m; if (m > bm) { bm = m; bj = 1; }
        m = fminf(md[2], d2); md[2] = m; if (m > bm) { bm = m; bj = 2; }
        m = fminf(md[3], d3); md[3] = m; if (m > bm) { bm = m; bj = 3; }

        unsigned hi = __float_as_uint(bm);
        unsigned lo = 0xFFFFFFFFu - (unsigned)(gbase + tid + bj * 512);
        unsigned m1 = __reduce_max_sync(0xffffffffu, hi);
        unsigned cnd = (hi == m1) ? lo : 0u;
        unsigned m2 = __reduce_max_sync(0xffffffffu, cnd);
        if (hi == m1 && lo == m2) {            // unique (indices unique)
            int w = tid >> 5;
            s_whi[w] = m1; s_wlo[w] = m2;
            s_wx[w] = pxs[bj]; s_wy[w] = pys[bj]; s_wz[w] = pzs[bj];
        }
        __syncthreads();
        if (tid < 32) {
            unsigned hi2 = (tid < 16) ? s_whi[tid] : 0u;
            unsigned lo2 = (tid < 16) ? s_wlo[tid] : 0u;
            unsigned M1 = __reduce_max_sync(0xffffffffu, hi2);
            unsigned c2 = (hi2 == M1) ? lo2 : 0u;
            unsigned M2 = __reduce_max_sync(0xffffffffu, c2);
            unsigned mb = __ballot_sync(0xffffffffu,
                                        (tid < 16) && hi2 == M1 && lo2 == M2);
            int wl = __ffs(mb) - 1;
            float x2 = __shfl_sync(0xffffffffu, s_wx[tid & 15], wl);
            float y2 = __shfl_sync(0xffffffffu, s_wy[tid & 15], wl);
            float z2 = __shfl_sync(0xffffffffu, s_wz[tid & 15], wl);
            if (tid < 8) {
                uint4 v; v.x = M2; v.y = M1;
                v.z = __float_as_uint(x2); v.w = __float_as_uint(y2);
                *(uint4*)cluster.map_shared_rank((void*)&s_sa[par][rank], tid) = v;
                *(float*)cluster.map_shared_rank((void*)&s_sz[par][rank], tid) = z2;
                unsigned ra;
                asm volatile("mapa.shared::cluster.u32 %0, %1, %2;"
                             : "=r"(ra) : "r"(mbar32), "r"(tid));
                asm volatile(
                    "mbarrier.arrive.release.cluster.shared::cluster.b64 _, [%0];"
                    :: "r"(ra) : "memory");
            }
            unsigned done = 0;
            while (!done) {
                asm volatile(
                    "{\n\t.reg .pred p;\n\t"
                    "mbarrier.try_wait.parity.acquire.cluster.shared::cta.b64 "
                    "p, [%1], %2, 0x989680;\n\t"
                    "selp.b32 %0, 1, 0, p;\n\t}"
                    : "=r"(done) : "r"(mbar32), "r"(phase) : "memory");
            }
        }
        __syncthreads();                       // releases all warps, orders smem
        {
            u64 bk = s_sa[par][0].key;
            int bs = 0;
#pragma unroll
            for (int s = 1; s < 8; ++s) {
                u64 k = s_sa[par][s].key;
                if (k > bk) { bk = k; bs = s; }
            }
            lx = s_sa[par][bs].x; ly = s_sa[par][bs].y; lz = s_sz[par][bs];
            if (rank == 0 && tid == 0) {
                qb[it * 3 + 0] = lx; qb[it * 3 + 1] = ly; qb[it * 3 + 2] = lz;
            }
        }
        par ^= 1;
        phase ^= 1;
    }
    cluster.sync();
}

// ---------------- FPS stage 1 (4096 -> 1024): 2-CTA cluster per batch -------
// Same exchange machinery as k_fps_cl, cluster size 2. Support = g_q0 (AoS),
// output = g_q1. Indices/keys identical to single-CTA version -> bit-exact.
__global__ __cluster_dims__(2, 1, 1) __launch_bounds__(512, 1)
void k_fps_cl2() {
    cg::cluster_group cluster = cg::this_cluster();
    const int rank = cluster.block_rank();
    const int b = blockIdx.x >> 1;
    const int tid = threadIdx.x;
    const int N = 4096, npoint = 1024;
    const int gbase = rank * 2048;            // 2048 pts per CTA

    __shared__ unsigned s_whi[16], s_wlo[16];
    __shared__ float s_wx[16], s_wy[16], s_wz[16];
    __shared__ SlotA s_sa[2][2];              // [parity][src rank]
    __shared__ float s_sz[2][2];
    __shared__ __align__(8) u64 s_mbar;

    const float* base = g_q0 + (size_t)b * 12288;

    u64 px01, px23, py01, py23, pz01, pz23;
    float pxs[4], pys[4], pzs[4], md[4];
    {
#pragma unroll
        for (int j = 0; j < 4; ++j) {
            const float* p = base + (size_t)(gbase + tid + j * 512) * 3;
            pxs[j] = p[0]; pys[j] = p[1]; pzs[j] = p[2];
            md[j] = 1e10f;
        }
        px01 = pack2(pxs[0], pxs[1]); px23 = pack2(pxs[2], pxs[3]);
        py01 = pack2(pys[0], pys[1]); py23 = pack2(pys[2], pys[3]);
        pz01 = pack2(pzs[0], pzs[1]); pz23 = pack2(pzs[2], pzs[3]);
    }

    unsigned mbar32 = (unsigned)__cvta_generic_to_shared(&s_mbar);
    if (tid == 0)
        asm volatile("mbarrier.init.shared.b64 [%0], %1;"
                     :: "r"(mbar32), "r"(2) : "memory");

    float* qb = g_q1 + (size_t)b * 3072;
    float lx = base[0], ly = base[1], lz = base[2];
    if (rank == 0 && tid == 0) { qb[0] = lx; qb[1] = ly; qb[2] = lz; }
    cluster.sync();

    int par = 0;
    unsigned phase = 0;
    for (int it = 1; it < npoint; ++it) {
        u64 nlx2 = pack2(-lx, -lx), nly2 = pack2(-ly, -ly), nlz2 = pack2(-lz, -lz);
        float d0, d1, d2, d3;
        {
            u64 dx = add2(px01, nlx2), dy = add2(py01, nly2), dz = add2(pz01, nlz2);
            u64 s = add2(add2(mul2(dx, dx), mul2(dy, dy)), mul2(dz, dz));
            unpack2(s, d0, d1);
        }
        {
            u64 dx = add2(px23, nlx2), dy = add2(py23, nly2), dz = add2(pz23, nlz2);
            u64 s = add2(add2(mul2(dx, dx), mul2(dy, dy)), mul2(dz, dz));
            unpack2(s, d2, d3);
        }
        float m, bm; int bj;
        m = fminf(md[0], d0); md[0] = m; bm = m; bj = 0;
        m = fminf(md[1], d1); md[1] = m; if (m > bm) { bm = m; bj = 1; }
        m = fminf(md[2], d2); md[2] = m; if (m > bm) { bm = m; bj = 2; }
        m = fminf(md[3], d3); md[3] = m; if (m > bm) { bm = m; bj = 3; }

        unsigned hi = __float_as_uint(bm);
        unsigned lo = 0xFFFFFFFFu - (unsigned)(gbase + tid + bj * 512);
        unsigned m1 = __reduce_max_sync(0xffffffffu, hi);
        unsigned cnd = (hi == m1) ? lo : 0u;
        unsigned m2 = __reduce_max_sync(0xffffffffu, cnd);
        if (hi == m1 && lo == m2) {
            int w = tid >> 5;
            s_whi[w] = m1; s_wlo[w] = m2;
            s_wx[w] = pxs[bj]; s_wy[w] = pys[bj]; s_wz[w] = pzs[bj];
        }
        __syncthreads();
        if (tid < 32) {
            unsigned hi2 = (tid < 16) ? s_whi[tid] : 0u;
            unsigned lo2 = (tid < 16) ? s_wlo[tid] : 0u;
            unsigned M1 = __reduce_max_sync(0xffffffffu, hi2);
            unsigned c2 = (hi2 == M1) ? lo2 : 0u;
            unsigned M2 = __reduce_max_sync(0xffffffffu, c2);
            unsigned mb = __ballot_sync(0xffffffffu,
                                        (tid < 16) && hi2 == M1 && lo2 == M2);
            int wl = __ffs(mb) - 1;
            float x2 = __shfl_sync(0xffffffffu, s_wx[tid & 15], wl);
            float y2 = __shfl_sync(0xffffffffu, s_wy[tid & 15], wl);
            float z2 = __shfl_sync(0xffffffffu, s_wz[tid & 15], wl);
            if (tid < 2) {
                uint4 v; v.x = M2; v.y = M1;
                v.z = __float_as_uint(x2); v.w = __float_as_uint(y2);
                *(uint4*)cluster.map_shared_rank((void*)&s_sa[par][rank], tid) = v;
                *(float*)cluster.map_shared_rank((void*)&s_sz[par][rank], tid) = z2;
                unsigned ra;
                asm volatile("mapa.shared::cluster.u32 %0, %1, %2;"
                             : "=r"(ra) : "r"(mbar32), "r"(tid));
                asm volatile(
                    "mbarrier.arrive.release.cluster.shared::cluster.b64 _, [%0];"
                    :: "r"(ra) : "memory");
            }
            unsigned done = 0;
            while (!done) {
                asm volatile(
                    "{\n\t.reg .pred p;\n\t"
                    "mbarrier.try_wait.parity.acquire.cluster.shared::cta.b64 "
                    "p, [%1], %2, 0x989680;\n\t"
                    "selp.b32 %0, 1, 0, p;\n\t}"
                    : "=r"(done) : "r"(mbar32), "r"(phase) : "memory");
            }
        }
        __syncthreads();
        {
            u64 k0 = s_sa[par][0].key;
            u64 k1 = s_sa[par][1].key;
            int bs = (k1 > k0) ? 1 : 0;
            lx = s_sa[par][bs].x; ly = s_sa[par][bs].y; lz = s_sz[par][bs];
            if (rank == 0 && tid == 0) {
                qb[it * 3 + 0] = lx; qb[it * 3 + 1] = ly; qb[it * 3 + 2] = lz;
            }
        }
        par ^= 1;
        phase ^= 1;
    }
    cluster.sync();
}

// ---------------- FPS stages 2-3: one CTA per batch --------------------------
__device__ void fps_stage_s(const float* __restrict__ sup, float* __restrict__ qout,
                            int N, int npoint,
                            unsigned* s_whi, unsigned* s_wlo,
                            float* s_wx, float* s_wy, float* s_wz, float* s_win) {
    int tid = threadIdx.x;
    float px[4], py[4], pz[4], md[4];
#pragma unroll
    for (int j = 0; j < 4; ++j) {
        int i = tid + j * 1024;
        md[j] = 1e10f;
        if (i < N) {
            const float* p = sup + (size_t)i * 3;
            px[j] = p[0]; py[j] = p[1]; pz[j] = p[2];
        } else { px[j] = 0.f; py[j] = 0.f; pz[j] = 0.f; }
    }
    float lx = sup[0], ly = sup[1], lz = sup[2];
    if (tid == 0) { qout[0] = lx; qout[1] = ly; qout[2] = lz; }
    bool valid = tid < N;

    for (int it = 1; it < npoint; ++it) {
        float bm = -1.f, bx = 0.f, by = 0.f, bz = 0.f;
        int bi = 0;
#pragma unroll
        for (int j = 0; j < 4; ++j) {
            int i = tid + j * 1024;
            if (i < N) {
                float dx = __fsub_rn(px[j], lx);
                float dy = __fsub_rn(py[j], ly);
                float dz = __fsub_rn(pz[j], lz);
                float d = d2_exact(dx, dy, dz);
                float m = fminf(md[j], d);
                md[j] = m;
                bool p = m > bm;
                bm = fmaxf(bm, m);
                bx = p ? px[j] : bx; by = p ? py[j] : by; bz = p ? pz[j] : bz;
                bi = p ? i : bi;
            }
        }
        unsigned hi = valid ? __float_as_uint(bm) : 0u;
        unsigned lo = valid ? (0xFFFFFFFFu - (unsigned)bi)
                            : (0xFFFFFFFFu - (unsigned)(N + tid));
        unsigned m1 = __reduce_max_sync(0xffffffffu, hi);
        unsigned cnd = (hi == m1) ? lo : 0u;
        unsigned m2 = __reduce_max_sync(0xffffffffu, cnd);
        if (hi == m1 && lo == m2) {
            int w = tid >> 5;
            s_whi[w] = m1; s_wlo[w] = m2;
            s_wx[w] = bx; s_wy[w] = by; s_wz[w] = bz;
        }
        __syncthreads();
        if (tid < 32) {
            unsigned hi2 = s_whi[tid], lo2 = s_wlo[tid];
            unsigned M1 = __reduce_max_sync(0xffffffffu, hi2);
            unsigned c2 = (hi2 == M1) ? lo2 : 0u;
            unsigned M2 = __reduce_max_sync(0xffffffffu, c2);
            unsigned mb = __ballot_sync(0xffffffffu, hi2 == M1 && lo2 == M2);
            int wl = __ffs(mb) - 1;
            float x2 = __shfl_sync(0xffffffffu, s_wx[tid], wl);
            float y2 = __shfl_sync(0xffffffffu, s_wy[tid], wl);
            float z2 = __shfl_sync(0xffffffffu, s_wz[tid], wl);
            if (tid == 0) {
                s_win[0] = x2; s_win[1] = y2; s_win[2] = z2;
                qout[it * 3 + 0] = x2; qout[it * 3 + 1] = y2; qout[it * 3 + 2] = z2;
            }
        }
        __syncthreads();
        lx = s_win[0]; ly = s_win[1]; lz = s_win[2];
    }
}

__global__ __launch_bounds__(1024, 1)
void k_fps_s23() {
    __shared__ unsigned s_whi[32], s_wlo[32];
    __shared__ float s_wx[32], s_wy[32], s_wz[32], s_win[3];
    int b = blockIdx.x;
    fps_stage_s(g_q1 + (size_t)b * 3072, g_q2 + (size_t)b * 768,
                1024, 256, s_whi, s_wlo, s_wx, s_wy, s_wz, s_win);
    __syncthreads();
    fps_stage_s(g_q2 + (size_t)b * 768, g_q3 + (size_t)b * 192,
                256, 64, s_whi, s_wlo, s_wx, s_wy, s_wz, s_win);
}

// ---------------- fused ball query + layer-1 (per-batch) ---------------------
__global__ __launch_bounds__(256)
void k_ball_l1(const float* __restrict__ ext, int scode, int qcode,
               const float* __restrict__ W, int CIN, int C1, int Q, int N,
               float r2, int b0) {
    extern __shared__ float sm[];
    float* wdp = sm;                           // [C1*3]
    int* sidx = (int*)(sm + C1 * 3);           // [8][32]
    int tid = threadIdx.x;
    for (int t = tid; t < C1 * 3; t += 256)
        wdp[t] = W[(t / 3) * CIN + (t % 3)];
    __syncthreads();

    int wi = tid >> 5, lane = tid & 31;
    int q = blockIdx.x * 8 + wi;
    if (q >= Q) return;
    const int b = b0;
    long long Nn = (long long)Q * 32;

    const float* qp = fbufc(qcode, nullptr) + b * bhalf(qcode) + (size_t)q * 3;
    float qx = qp[0], qy = qp[1], qz = qp[2];
    const float* sp = (scode < 0) ? ext + (size_t)b * N * 3
                                  : fbufc(scode, nullptr) + b * bhalf(scode);
    int* o = sidx + wi * 32;

    int cnt = 0, first = 0;
    for (int base = 0; base < N; base += 128) {    // N % 128 == 0 always
        float d2v[4];
#pragma unroll
        for (int j = 0; j < 4; ++j) {
            int i = base + j * 32 + lane;
            float dx = __fsub_rn(qx, __ldg(sp + i * 3 + 0));
            float dy = __fsub_rn(qy, __ldg(sp + i * 3 + 1));
            float dz = __fsub_rn(qz, __ldg(sp + i * 3 + 2));
            d2v[j] = d2_exact(dx, dy, dz);
        }
#pragma unroll
        for (int j = 0; j < 4; ++j) {
            bool hit = d2v[j] < r2;
            unsigned m = __ballot_sync(0xffffffffu, hit);
            if (cnt == 0 && m) first = base + j * 32 + __ffs(m) - 1;
            if (hit) {
                int pos = cnt + __popc(m & ((1u << lane) - 1u));
                if (pos < 32) o[pos] = base + j * 32 + lane;
            }
            cnt += __popc(m);
        }
        if (cnt >= 32) break;
    }
    for (int pos = cnt + lane; pos < 32; pos += 32) o[pos] = first;
    __syncwarp();

    int idx = o[lane];
    const float* spp = sp + (size_t)idx * 3;
    float dx = __fsub_rn(spp[0], qx);
    float dy = __fsub_rn(spp[1], qy);
    float dz = __fsub_rn(spp[2], qz);

    const float* Pb = g_P + b * 2097152u + idx;
    float* oh = g_h1 + b * 8388608u + (size_t)q * 32 + lane;
#pragma unroll 8
    for (int c = 0; c < C1; ++c) {
        float v = __ldg(Pb + (size_t)c * N);
        v = fmaf(wdp[c * 3 + 0], dx,
            fmaf(wdp[c * 3 + 1], dy,
            fmaf(wdp[c * 3 + 2], dz, v)));
        oh[(size_t)c * Nn] = v > 0.f ? v : 0.f;
    }
}

// ---------------- GEMM: Y = act(W @ X + bias), optional fused max-pool ------
template <int BM, int BK, int TM, bool POOL, bool RELU, bool GUARD>
__global__ __launch_bounds__(256, 2)
void k_gemm(const float* __restrict__ Wt, const float* __restrict__ bias,
            int xcode, int ycode, float* yext, int M, int K, int ldw,
            long long Nn, int b0) {
    __shared__ __align__(16) float As[2][BK][BM];
    __shared__ __align__(16) float Bs[2][BK][128];
    int b = blockIdx.z + b0;
    const float* X = fbufc(xcode, nullptr) + b * bhalf(xcode);
    int tid = threadIdx.x;
    int tm = tid >> 4, tn = tid & 15;
    int rowBase = blockIdx.y * BM;
    long long colBase = (long long)blockIdx.x * 128;

    float acc[TM][8];
#pragma unroll
    for (int i = 0; i < TM; ++i)
#pragma unroll
        for (int j = 0; j < 8; ++j) acc[i][j] = 0.f;

    if (GUARD) {
        for (int k0 = 0; k0 < K; k0 += BK) {
#pragma unroll
            for (int t = tid; t < BM * BK; t += 256) {
                int m = t / BK, kk = t % BK;
                As[0][kk][m] = (k0 + kk < K)
                    ? Wt[(size_t)(rowBase + m) * ldw + k0 + kk] : 0.f;
            }
#pragma unroll
            for (int t = tid; t < BK * 128; t += 256) {
                int kk = t >> 7, nn = t & 127;
                Bs[0][kk][nn] = (k0 + kk < K)
                    ? X[(size_t)(k0 + kk) * Nn + colBase + nn] : 0.f;
            }
            __syncthreads();
#pragma unroll
            for (int kk = 0; kk < BK; ++kk) {
                float a[TM], bb[8];
#pragma unroll
                for (int v = 0; v < TM / 4; ++v) {
                    float4 a4 = *reinterpret_cast<const float4*>(&As[0][kk][tm * TM + 4 * v]);
                    a[4 * v] = a4.x; a[4 * v + 1] = a4.y;
                    a[4 * v + 2] = a4.z; a[4 * v + 3] = a4.w;
                }
                float4 b0v = *reinterpret_cast<const float4*>(&Bs[0][kk][tn * 8]);
                float4 b1v = *reinterpret_cast<const float4*>(&Bs[0][kk][tn * 8 + 4]);
                bb[0] = b0v.x; bb[1] = b0v.y; bb[2] = b0v.z; bb[3] = b0v.w;
                bb[4] = b1v.x; bb[5] = b1v.y; bb[6] = b1v.z; bb[7] = b1v.w;
#pragma unroll
                for (int i = 0; i < TM; ++i)
#pragma unroll
                    for (int j = 0; j < 8; ++j)
                        acc[i][j] = fmaf(a[i], bb[j], acc[i][j]);
            }
            __syncthreads();
        }
    } else {
        constexpr int APT = BM * BK / 256;
        constexpr int TPR = BK / APT;
        constexpr int BQ = BK / 8;
        const int a_m = tid / TPR;
        const int a_k = (tid % TPR) * APT;
        const int b_k = tid >> 5;
        const int b_c = (tid & 31) * 4;

        const float* Arow = Wt + (size_t)(rowBase + a_m) * ldw + a_k;
        const float* Bcol = X + colBase + b_c;

        float ra[APT];
        float4 rb[BQ];
#pragma unroll
        for (int i = 0; i < APT; ++i) As[0][a_k + i][a_m] = Arow[i];
#pragma unroll
        for (int v = 0; v < BQ; ++v) {
            int kk = b_k + v * 8;
            *(float4*)&Bs[0][kk][b_c] = *(const float4*)(Bcol + (size_t)kk * Nn);
        }
        __syncthreads();

        const int ntiles = K / BK;
        for (int t = 0; t < ntiles; ++t) {
            int cur = t & 1;
            if (t + 1 < ntiles) {
                const float* An = Arow + (t + 1) * BK;
#pragma unroll
                for (int i = 0; i < APT; ++i) ra[i] = An[i];
#pragma unroll
                for (int v = 0; v < BQ; ++v) {
                    int kk = b_k + v * 8;
                    rb[v] = *(const float4*)(Bcol + (size_t)((t + 1) * BK + kk) * Nn);
                }
            }
#pragma unroll
            for (int kk = 0; kk < BK; ++kk) {
                float a[TM], bb[8];
#pragma unroll
                for (int v = 0; v < TM / 4; ++v) {
                    float4 a4 = *reinterpret_cast<const float4*>(&As[cur][kk][tm * TM + 4 * v]);
                    a[4 * v] = a4.x; a[4 * v + 1] = a4.y;
                    a[4 * v + 2] = a4.z; a[4 * v + 3] = a4.w;
                }
                float4 b0v = *reinterpret_cast<const float4*>(&Bs[cur][kk][tn * 8]);
                float4 b1v = *reinterpret_cast<const float4*>(&Bs[cur][kk][tn * 8 + 4]);
                bb[0] = b0v.x; bb[1] = b0v.y; bb[2] = b0v.z; bb[3] = b0v.w;
                bb[4] = b1v.x; bb[5] = b1v.y; bb[6] = b1v.z; bb[7] = b1v.w;
#pragma unroll
                for (int i = 0; i < TM; ++i)
#pragma unroll
                    for (int j = 0; j < 8; ++j)
                        acc[i][j] = fmaf(a[i], bb[j], acc[i][j]);
            }
            if (t + 1 < ntiles) {
                int nxt = cur ^ 1;
#pragma unroll
                for (int i = 0; i < APT; ++i) As[nxt][a_k + i][a_m] = ra[i];
#pragma unroll
                for (int v = 0; v < BQ; ++v)
                    *(float4*)&Bs[nxt][b_k + v * 8][b_c] = rb[v];
            }
            __syncthreads();
        }
    }

    if (!POOL) {
        float* Y = fbufw(ycode, nullptr) + b * bhalf(ycode);
#pragma unroll
        for (int i = 0; i < TM; ++i) {
            int row = rowBase + tm * TM + i;
            float bv = bias[row];
            float* yr = Y + (size_t)row * Nn + colBase + tn * 8;
#pragma unroll
            for (int j = 0; j < 8; ++j) {
                float v = acc[i][j] + bv;
                yr[j] = RELU ? (v > 0.f ? v : 0.f) : v;
            }
        }
    } else {
        long long Q = Nn >> 5;
        float* Y = (ycode < 0) ? yext + (size_t)b * M * Q
                               : fbufw(ycode, nullptr) + b * bhalf(ycode);
#pragma unroll
        for (int i = 0; i < TM; ++i) {
            float m = acc[i][0];
#pragma unroll
            for (int j = 1; j < 8; ++j) m = fmaxf(m, acc[i][j]);
            m = fmaxf(m, __shfl_xor_sync(0xffffffffu, m, 1));
            m = fmaxf(m, __shfl_xor_sync(0xffffffffu, m, 2));
            if ((tn & 3) == 0) {
                int row = rowBase + tm * TM + i;
                float v = m + bias[row];
                long long q = (colBase >> 5) + (tn >> 2);
                Y[(size_t)row * Q + q] = v > 0.f ? v : 0.f;
            }
        }
    }
}

// ---------------- stream/event handles (created at load, before harness) ----
struct HxStreams {
    cudaStream_t s2, s4;
    cudaEvent_t evT, evA, evP, evB1, evB2, evD;
    bool ok;
    HxStreams() {
        ok = cudaStreamCreateWithFlags(&s2, cudaStreamNonBlocking) == cudaSuccess
          && cudaStreamCreateWithFlags(&s4, cudaStreamNonBlocking) == cudaSuccess
          && cudaEventCreateWithFlags(&evT, cudaEventDisableTiming) == cudaSuccess
          && cudaEventCreateWithFlags(&evA, cudaEventDisableTiming) == cudaSuccess
          && cudaEventCreateWithFlags(&evP, cudaEventDisableTiming) == cudaSuccess
          && cudaEventCreateWithFlags(&evB1, cudaEventDisableTiming) == cudaSuccess
          && cudaEventCreateWithFlags(&evB2, cudaEventDisableTiming) == cudaSuccess
          && cudaEventCreateWithFlags(&evD, cudaEventDisableTiming) == cudaSuccess;
    }
};
static HxStreams g_hx;

// ---------------------------------------------------------------------------
extern "C" void kernel_launch(void* const* d_in, const int* in_sizes, int n_in,
                              void* d_out, int out_size) {
    (void)in_sizes; (void)n_in; (void)out_size;
    const float* xyz = (const float*)d_in[0];
    const float* W[4][3]; const float* BV[4][3];
    {
        int p = 1;
        for (int k = 0; k < 4; ++k)
            for (int l = 0; l < 3; ++l) {
                W[k][l]  = (const float*)d_in[p++];
                BV[k][l] = (const float*)d_in[p++];
            }
    }

    static const int   Ns[4]  = {16384, 4096, 1024, 256};
    static const int   CIN[4] = {6, 131, 259, 515};
    static const int   C1[4]  = {64, 128, 256, 512};
    static const int   C2[4]  = {64, 128, 256, 512};
    static const int   C3[4]  = {128, 256, 512, 1024};
    static const float R2[4]  = {(float)(0.1 * 0.1), (float)(0.2 * 0.2),
                                 (float)(0.4 * 0.4), (float)(0.8 * 0.8)};
    static const int supc[4] = {-1, 6, 7, 8};   // support xyz buffer
    static const int qc[4]   = {6, 7, 8, 9};    // query   xyz buffer
    static const int fic[4]  = {5, 3, 4, 3};    // feats-in buffer
    static const int foc[4]  = {3, 4, 3, -1};   // pooled feats-out

    auto gemm = [&](cudaStream_t st, const float* Wp, const float* bp,
                    int xc, int yc, float* ye, int M, int K, int ldw,
                    long long Nn, bool pool, bool relu, int b0, int zdim) {
        bool guard = (K % 16) != 0;
        if (M >= 128) {
            dim3 g((unsigned)(Nn / 128), M / 128, zdim);
            if (guard) {
                if (pool) k_gemm<128, 16, 8, true,  true,  true ><<<g, 256, 0, st>>>(Wp, bp, xc, yc, ye, M, K, ldw, Nn, b0);
                else if (relu) k_gemm<128, 16, 8, false, true,  true ><<<g, 256, 0, st>>>(Wp, bp, xc, yc, ye, M, K, ldw, Nn, b0);
                else k_gemm<128, 16, 8, false, false, true ><<<g, 256, 0, st>>>(Wp, bp, xc, yc, ye, M, K, ldw, Nn, b0);
            } else {
                if (pool) k_gemm<128, 16, 8, true,  true,  false><<<g, 256, 0, st>>>(Wp, bp, xc, yc, ye, M, K, ldw, Nn, b0);
                else if (relu) k_gemm<128, 16, 8, false, true,  false><<<g, 256, 0, st>>>(Wp, bp, xc, yc, ye, M, K, ldw, Nn, b0);
                else k_gemm<128, 16, 8, false, false, false><<<g, 256, 0, st>>>(Wp, bp, xc, yc, ye, M, K, ldw, Nn, b0);
            }
        } else {
            dim3 g((unsigned)(Nn / 128), M / 64, zdim);
            if (guard) {
                if (pool) k_gemm<64, 16, 4, true,  true,  true ><<<g, 256, 0, st>>>(Wp, bp, xc, yc, ye, M, K, ldw, Nn, b0);
                else if (relu) k_gemm<64, 16, 4, false, true,  true ><<<g, 256, 0, st>>>(Wp, bp, xc, yc, ye, M, K, ldw, Nn, b0);
                else k_gemm<64, 16, 4, false, false, true ><<<g, 256, 0, st>>>(Wp, bp, xc, yc, ye, M, K, ldw, Nn, b0);
            } else {
                if (pool) k_gemm<64, 16, 4, true,  true,  false><<<g, 256, 0, st>>>(Wp, bp, xc, yc, ye, M, K, ldw, Nn, b0);
                else if (relu) k_gemm<64, 16, 4, false, true,  false><<<g, 256, 0, st>>>(Wp, bp, xc, yc, ye, M, K, ldw, Nn, b0);
                else k_gemm<64, 16, 4, false, false, false><<<g, 256, 0, st>>>(Wp, bp, xc, yc, ye, M, K, ldw, Nn, b0);
            }
        }
    };

    auto ball = [&](cudaStream_t st, int k, int b) {
        int N = Ns[k], Q = N / 4;
        size_t smem = (size_t)C1[k] * 3 * 4 + 8 * 32 * 4;
        k_ball_l1<<<Q / 8, 256, smem, st>>>(
            xyz, supc[k], qc[k], W[k][0], CIN[k], C1[k], Q, N, R2[k], b);
    };

    // per-batch stage chain (stages 0..3); P0 must already be done.
    auto chain = [&](cudaStream_t sb, int b, bool ov) {
        for (int k = 0; k < 4; ++k) {
            int N = Ns[k], Q = N / 4;
            long long Nn = (long long)Q * 32;
            if (k >= 1)
                gemm(sb, W[k][0] + 3, BV[k][0], fic[k], 0, nullptr,
                     C1[k], CIN[k] - 3, CIN[k], (long long)N, false, false, b, 1);
            if (k == 1 && ov) cudaStreamWaitEvent(sb, g_hx.evB1, 0);  // q1 ready
            if (k == 2 && ov) cudaStreamWaitEvent(sb, g_hx.evB2, 0);  // q2/q3 ready
            ball(sb, k, b);
            gemm(sb, W[k][1], BV[k][1], 1, 2, nullptr,
                 C2[k], C1[k], C1[k], Nn, false, true, b, 1);
            gemm(sb, W[k][2], BV[k][2], 2, foc[k], (float*)d_out,
                 C3[k], C2[k], C2[k], Nn, true, true, b, 1);
        }
    };

    const bool ov = g_hx.ok;

    if (ov) {
        cudaStream_t s2 = g_hx.s2, s4 = g_hx.s4;
        // s0: transpose -> evT -> FPS0 (alone on the chip) -> evA
        k_transpose<<<(2 * 16384 + 255) / 256, 256>>>(xyz);
        cudaEventRecord(g_hx.evT, 0);
        k_fps_cl<<<16, 512>>>(xyz, 16384, 4096);
        cudaEventRecord(g_hx.evA, 0);
        // s2: P0 (both batches, tiny) under FPS0; then stage-1 FPS (2-CTA
        // cluster per batch) -> evB1; then stages 2-3 -> evB2
        cudaStreamWaitEvent(s2, g_hx.evT, 0);
        gemm(s2, W[0][0] + 3, BV[0][0], fic[0], 0, nullptr,
             C1[0], CIN[0] - 3, CIN[0], 16384LL, false, false, 0, 2);
        cudaEventRecord(g_hx.evP, s2);
        cudaStreamWaitEvent(s2, g_hx.evA, 0);
        k_fps_cl2<<<4, 512, 0, s2>>>();
        cudaEventRecord(g_hx.evB1, s2);
        k_fps_s23<<<2, 1024, 0, s2>>>();
        cudaEventRecord(g_hx.evB2, s2);
        // batch 0 chain on s0 (after fps_cl in program order; needs P0)
        cudaStreamWaitEvent(0, g_hx.evP, 0);
        // batch 1 chain on s4 (fork via in-graph events evA + evP)
        cudaStreamWaitEvent(s4, g_hx.evA, 0);
        cudaStreamWaitEvent(s4, g_hx.evP, 0);
        chain(s4, 1, true);
        cudaEventRecord(g_hx.evD, s4);
        chain(0, 0, true);
        cudaStreamWaitEvent(0, g_hx.evD, 0);             // join batch-1 chain
    } else {
        // sequential fallback
        k_transpose<<<(2 * 16384 + 255) / 256, 256>>>(xyz);
        k_fps_cl<<<16, 512>>>(xyz, 16384, 4096);
        k_fps_cl2<<<4, 512>>>();
        k_fps_s23<<<2, 1024>>>();
        gemm(0, W[0][0] + 3, BV[0][0], fic[0], 0, nullptr,
             C1[0], CIN[0] - 3, CIN[0], 16384LL, false, false, 0, 2);
        for (int k = 0; k < 4; ++k) {
            int N = Ns[k], Q = N / 4;
            long long Nn = (long long)Q * 32;
            if (k >= 1)
                gemm(0, W[k][0] + 3, BV[k][0], fic[k], 0, nullptr,
                     C1[k], CIN[k] - 3, CIN[k], (long long)N, false, false, 0, 2);
            ball(0, k, 0);
            ball(0, k, 1);
            gemm(0, W[k][1], BV[k][1], 1, 2, nullptr,
                 C2[k], C1[k], C1[k], Nn, false, true, 0, 2);
            gemm(0, W[k][2], BV[k][2], 2, foc[k], (float*)d_out,
                 C3[k], C2[k], C2[k], Nn, true, true, 0, 2);
        }
    }
}

// round 16
// speedup vs baseline: 1.0651x; 1.0651x over previous
#include <cuda_runtime.h>
#include <cuda_bf16.h>
#include <cooperative_groups.h>

namespace cg = cooperative_groups;
typedef unsigned long long u64;

// ---------------------------------------------------------------------------
// PointNet++ encoder, B=2, N=16384, 4 SA stages (stride 4, nsample 32)
// ---------------------------------------------------------------------------

// ---------------- scratch buffers (device globals; no allocs allowed) ------
// Internal buffers use FIXED per-batch half strides (bhalf) so the two batch
// pipelines can be at different stages concurrently without overlap.
__device__ float g_P[4194304];     // projected feats P   half = 2097152
__device__ float g_h1[16777216];   // layer-1 out         half = 8388608
__device__ float g_h2[16777216];   // layer-2 out         half = 8388608
__device__ float g_fA[1048576];    // pooled feats ping   half = 524288
__device__ float g_fB[1048576];    // pooled feats pong   half = 524288
__device__ float g_feats0[98304];  // xyz^T               half = 49152
__device__ float g_q0[24576];      // stage0 query xyz    half = 12288
__device__ float g_q1[6144];       // stage1 query xyz    half = 3072
__device__ float g_q2[1536];       // stage2 query xyz    half = 768
__device__ float g_q3[384];        // stage3 query xyz    half = 192

__device__ __forceinline__ const float* fbufc(int code, const float* ext) {
    switch (code) {
        case 0: return g_P;   case 1: return g_h1;  case 2: return g_h2;
        case 3: return g_fA;  case 4: return g_fB;  case 5: return g_feats0;
        case 6: return g_q0;  case 7: return g_q1;  case 8: return g_q2;
        case 9: return g_q3;  default: return ext;
    }
}
__device__ __forceinline__ float* fbufw(int code, float* ext) {
    switch (code) {
        case 0: return g_P;   case 1: return g_h1;  case 2: return g_h2;
        case 3: return g_fA;  case 4: return g_fB;  case 5: return g_feats0;
        case 6: return g_q0;  case 7: return g_q1;  case 8: return g_q2;
        case 9: return g_q3;  default: return ext;
    }
}
__device__ __forceinline__ size_t bhalf(int code) {
    switch (code) {
        case 0: return 2097152u;  case 1: return 8388608u; case 2: return 8388608u;
        case 3: return 524288u;   case 4: return 524288u;  case 5: return 49152u;
        case 6: return 12288u;    case 7: return 3072u;    case 8: return 768u;
        case 9: return 192u;      default: return 0u;
    }
}

// d2 exactly as JAX computes it: ((dx*dx + dy*dy) + dz*dz), no FMA contraction
__device__ __forceinline__ float d2_exact(float dx, float dy, float dz) {
    return __fadd_rn(__fadd_rn(__fmul_rn(dx, dx), __fmul_rn(dy, dy)),
                     __fmul_rn(dz, dz));
}

// ---- packed f32x2 helpers (rn mul/add: per-lane bit-identical to scalar) ---
__device__ __forceinline__ u64 pack2(float lo, float hi) {
    u64 r; asm("mov.b64 %0,{%1,%2};" : "=l"(r) : "f"(lo), "f"(hi)); return r;
}
__device__ __forceinline__ void unpack2(u64 v, float& lo, float& hi) {
    asm("mov.b64 {%0,%1},%2;" : "=f"(lo), "=f"(hi) : "l"(v));
}
__device__ __forceinline__ u64 add2(u64 a, u64 b) {
    u64 r; asm("add.rn.f32x2 %0,%1,%2;" : "=l"(r) : "l"(a), "l"(b)); return r;
}
__device__ __forceinline__ u64 mul2(u64 a, u64 b) {
    u64 r; asm("mul.rn.f32x2 %0,%1,%2;" : "=l"(r) : "l"(a), "l"(b)); return r;
}

// ---------------- feats0 = xyz^T  [B,3,N] -----------------------------------
__global__ void k_transpose(const float* __restrict__ xyz) {
    int i = blockIdx.x * blockDim.x + threadIdx.x;
    if (i >= 2 * 16384) return;
    int b = i >> 14, n = i & 16383;
#pragma unroll
    for (int c = 0; c < 3; ++c)
        g_feats0[b * 49152 + c * 16384 + n] = xyz[(size_t)i * 3 + c];
}

// ---------------- FPS stage 0: 8-CTA cluster per batch (N=16384) ------------
struct __align__(16) SlotA { u64 key; float x, y; };

__global__ __cluster_dims__(8, 1, 1) __launch_bounds__(512, 1)
void k_fps_cl(const float* __restrict__ xyz, int N, int npoint) {
    cg::cluster_group cluster = cg::this_cluster();
    const int rank = cluster.block_rank();
    const int b = blockIdx.x >> 3;
    const int tid = threadIdx.x;
    const int gbase = rank * (N >> 3);        // 2048 pts per CTA

    __shared__ unsigned s_whi[16], s_wlo[16];
    __shared__ float s_wx[16], s_wy[16], s_wz[16];
    __shared__ SlotA s_sa[2][8];              // [parity][src rank]
    __shared__ float s_sz[2][8];
    __shared__ __align__(8) u64 s_mbar;

    const float* base = xyz + (size_t)b * N * 3;

    u64 px01, px23, py01, py23, pz01, pz23;
    float pxs[4], pys[4], pzs[4], md[4];
    {
#pragma unroll
        for (int j = 0; j < 4; ++j) {
            const float* p = base + (size_t)(gbase + tid + j * 512) * 3;
            pxs[j] = p[0]; pys[j] = p[1]; pzs[j] = p[2];
            md[j] = 1e10f;
        }
        px01 = pack2(pxs[0], pxs[1]); px23 = pack2(pxs[2], pxs[3]);
        py01 = pack2(pys[0], pys[1]); py23 = pack2(pys[2], pys[3]);
        pz01 = pack2(pzs[0], pzs[1]); pz23 = pack2(pzs[2], pzs[3]);
    }

    unsigned mbar32 = (unsigned)__cvta_generic_to_shared(&s_mbar);
    if (tid == 0)
        asm volatile("mbarrier.init.shared.b64 [%0], %1;"
                     :: "r"(mbar32), "r"(8) : "memory");

    float* qb = g_q0 + (size_t)b * 12288;
    float lx = base[0], ly = base[1], lz = base[2];
    if (rank == 0 && tid == 0) { qb[0] = lx; qb[1] = ly; qb[2] = lz; }
    cluster.sync();                            // mbarriers + slots live

    int par = 0;
    unsigned phase = 0;
    for (int it = 1; it < npoint; ++it) {
        u64 nlx2 = pack2(-lx, -lx), nly2 = pack2(-ly, -ly), nlz2 = pack2(-lz, -lz);
        float d0, d1, d2, d3;
        {
            u64 dx = add2(px01, nlx2), dy = add2(py01, nly2), dz = add2(pz01, nlz2);
            u64 s = add2(add2(mul2(dx, dx), mul2(dy, dy)), mul2(dz, dz));
            unpack2(s, d0, d1);
        }
        {
            u64 dx = add2(px23, nlx2), dy = add2(py23, nly2), dz = add2(pz23, nlz2);
            u64 s = add2(add2(mul2(dx, dx), mul2(dy, dy)), mul2(dz, dz));
            unpack2(s, d2, d3);
        }
        float m, bm; int bj;
        m = fminf(md[0], d0); md[0] = m; bm = m; bj = 0;
        m = fminf(md[1], d1); md[1] = m; if (m > bm) { bm = m; bj = 1; }
        m = fminf(md[2], d2); md[2] = m; if (m > bm) { bm = m; bj = 2; }
        m = fminf(md[3], d3); md[3] = m; if (m > bm) { bm = m; bj = 3; }

        unsigned hi = __float_as_uint(bm);
        unsigned lo = 0xFFFFFFFFu - (unsigned)(gbase + tid + bj * 512);
        unsigned m1 = __reduce_max_sync(0xffffffffu, hi);
        unsigned cnd = (hi == m1) ? lo : 0u;
        unsigned m2 = __reduce_max_sync(0xffffffffu, cnd);
        if (hi == m1 && lo == m2) {            // unique (indices unique)
            int w = tid >> 5;
            s_whi[w] = m1; s_wlo[w] = m2;
            s_wx[w] = pxs[bj]; s_wy[w] = pys[bj]; s_wz[w] = pzs[bj];
        }
        __syncthreads();
        if (tid < 32) {
            unsigned hi2 = (tid < 16) ? s_whi[tid] : 0u;
            unsigned lo2 = (tid < 16) ? s_wlo[tid] : 0u;
            unsigned M1 = __reduce_max_sync(0xffffffffu, hi2);
            unsigned c2 = (hi2 == M1) ? lo2 : 0u;
            unsigned M2 = __reduce_max_sync(0xffffffffu, c2);
            unsigned mb = __ballot_sync(0xffffffffu,
                                        (tid < 16) && hi2 == M1 && lo2 == M2);
            int wl = __ffs(mb) - 1;
            float x2 = __shfl_sync(0xffffffffu, s_wx[tid & 15], wl);
            float y2 = __shfl_sync(0xffffffffu, s_wy[tid & 15], wl);
            float z2 = __shfl_sync(0xffffffffu, s_wz[tid & 15], wl);
            if (tid < 8) {
                uint4 v; v.x = M2; v.y = M1;
                v.z = __float_as_uint(x2); v.w = __float_as_uint(y2);
                *(uint4*)cluster.map_shared_rank((void*)&s_sa[par][rank], tid) = v;
                *(float*)cluster.map_shared_rank((void*)&s_sz[par][rank], tid) = z2;
                unsigned ra;
                asm volatile("mapa.shared::cluster.u32 %0, %1, %2;"
                             : "=r"(ra) : "r"(mbar32), "r"(tid));
                asm volatile(
                    "mbarrier.arrive.release.cluster.shared::cluster.b64 _, [%0];"
                    :: "r"(ra) : "memory");
            }
            unsigned done = 0;
            while (!done) {
                asm volatile(
                    "{\n\t.reg .pred p;\n\t"
                    "mbarrier.try_wait.parity.acquire.cluster.shared::cta.b64 "
                    "p, [%1], %2, 0x989680;\n\t"
                    "selp.b32 %0, 1, 0, p;\n\t}"
                    : "=r"(done) : "r"(mbar32), "r"(phase) : "memory");
            }
        }
        __syncthreads();                       // releases all warps, orders smem
        {
            u64 bk = s_sa[par][0].key;
            int bs = 0;
#pragma unroll
            for (int s = 1; s < 8; ++s) {
                u64 k = s_sa[par][s].key;
                if (k > bk) { bk = k; bs = s; }
            }
            lx = s_sa[par][bs].x; ly = s_sa[par][bs].y; lz = s_sz[par][bs];
            if (rank == 0 && tid == 0) {
                qb[it * 3 + 0] = lx; qb[it * 3 + 1] = ly; qb[it * 3 + 2] = lz;
            }
        }
        par ^= 1;
        phase ^= 1;
    }
    cluster.sync();
}

// ---------------- FPS stages 1-3: one CTA per batch --------------------------
template <bool FULL>
__device__ void fps_stage(const float* __restrict__ sup, float* __restrict__ qout,
                          int N, int npoint,
                          unsigned* s_whi, unsigned* s_wlo,
                          float* s_wx, float* s_wy, float* s_wz, float* s_win) {
    int tid = threadIdx.x;
    float px[4], py[4], pz[4], md[4];
#pragma unroll
    for (int j = 0; j < 4; ++j) {
        int i = tid + j * 1024;
        md[j] = 1e10f;
        if (FULL || i < N) {
            const float* p = sup + (size_t)i * 3;
            px[j] = p[0]; py[j] = p[1]; pz[j] = p[2];
        } else { px[j] = 0.f; py[j] = 0.f; pz[j] = 0.f; }
    }
    u64 px01, px23, py01, py23, pz01, pz23;
    if (FULL) {
        px01 = pack2(px[0], px[1]); px23 = pack2(px[2], px[3]);
        py01 = pack2(py[0], py[1]); py23 = pack2(py[2], py[3]);
        pz01 = pack2(pz[0], pz[1]); pz23 = pack2(pz[2], pz[3]);
    }
    float lx = sup[0], ly = sup[1], lz = sup[2];
    if (tid == 0) { qout[0] = lx; qout[1] = ly; qout[2] = lz; }
    bool valid = tid < N;

    for (int it = 1; it < npoint; ++it) {
        float bm = -1.f, bx = 0.f, by = 0.f, bz = 0.f;
        int bi = 0;
        if (FULL) {
            u64 nlx2 = pack2(-lx, -lx), nly2 = pack2(-ly, -ly), nlz2 = pack2(-lz, -lz);
            float d0, d1, d2, d3;
            {
                u64 dx = add2(px01, nlx2), dy = add2(py01, nly2), dz = add2(pz01, nlz2);
                u64 s = add2(add2(mul2(dx, dx), mul2(dy, dy)), mul2(dz, dz));
                unpack2(s, d0, d1);
            }
            {
                u64 dx = add2(px23, nlx2), dy = add2(py23, nly2), dz = add2(pz23, nlz2);
                u64 s = add2(add2(mul2(dx, dx), mul2(dy, dy)), mul2(dz, dz));
                unpack2(s, d2, d3);
            }
            float m; int bj;
            m = fminf(md[0], d0); md[0] = m; bm = m; bj = 0;
            m = fminf(md[1], d1); md[1] = m; if (m > bm) { bm = m; bj = 1; }
            m = fminf(md[2], d2); md[2] = m; if (m > bm) { bm = m; bj = 2; }
            m = fminf(md[3], d3); md[3] = m; if (m > bm) { bm = m; bj = 3; }
            bx = px[bj]; by = py[bj]; bz = pz[bj];
            bi = tid + bj * 1024;
        } else {
#pragma unroll
            for (int j = 0; j < 4; ++j) {
                int i = tid + j * 1024;
                if (i < N) {
                    float dx = __fsub_rn(px[j], lx);
                    float dy = __fsub_rn(py[j], ly);
                    float dz = __fsub_rn(pz[j], lz);
                    float d = d2_exact(dx, dy, dz);
                    float m = fminf(md[j], d);
                    md[j] = m;
                    bool p = m > bm;
                    bm = fmaxf(bm, m);
                    bx = p ? px[j] : bx; by = p ? py[j] : by; bz = p ? pz[j] : bz;
                    bi = p ? i : bi;
                }
            }
        }
        unsigned hi = valid ? __float_as_uint(bm) : 0u;
        unsigned lo = valid ? (0xFFFFFFFFu - (unsigned)bi)
                            : (0xFFFFFFFFu - (unsigned)(N + tid));
        unsigned m1 = __reduce_max_sync(0xffffffffu, hi);
        unsigned cnd = (hi == m1) ? lo : 0u;
        unsigned m2 = __reduce_max_sync(0xffffffffu, cnd);
        if (hi == m1 && lo == m2) {
            int w = tid >> 5;
            s_whi[w] = m1; s_wlo[w] = m2;
            s_wx[w] = bx; s_wy[w] = by; s_wz[w] = bz;
        }
        __syncthreads();
        if (tid < 32) {
            unsigned hi2 = s_whi[tid], lo2 = s_wlo[tid];
            unsigned M1 = __reduce_max_sync(0xffffffffu, hi2);
            unsigned c2 = (hi2 == M1) ? lo2 : 0u;
            unsigned M2 = __reduce_max_sync(0xffffffffu, c2);
            unsigned mb = __ballot_sync(0xffffffffu, hi2 == M1 && lo2 == M2);
            int wl = __ffs(mb) - 1;
            float x2 = __shfl_sync(0xffffffffu, s_wx[tid], wl);
            float y2 = __shfl_sync(0xffffffffu, s_wy[tid], wl);
            float z2 = __shfl_sync(0xffffffffu, s_wz[tid], wl);
            if (tid == 0) {
                s_win[0] = x2; s_win[1] = y2; s_win[2] = z2;
                qout[it * 3 + 0] = x2; qout[it * 3 + 1] = y2; qout[it * 3 + 2] = z2;
            }
        }
        __syncthreads();
        lx = s_win[0]; ly = s_win[1]; lz = s_win[2];
    }
}

__global__ __launch_bounds__(1024, 1)
void k_fps_s1() {
    __shared__ unsigned s_whi[32], s_wlo[32];
    __shared__ float s_wx[32], s_wy[32], s_wz[32], s_win[3];
    int b = blockIdx.x;
    fps_stage<true >(g_q0 + (size_t)b * 12288, g_q1 + (size_t)b * 3072,
                     4096, 1024, s_whi, s_wlo, s_wx, s_wy, s_wz, s_win);
}

__global__ __launch_bounds__(1024, 1)
void k_fps_s23() {
    __shared__ unsigned s_whi[32], s_wlo[32];
    __shared__ float s_wx[32], s_wy[32], s_wz[32], s_win[3];
    int b = blockIdx.x;
    fps_stage<false>(g_q1 + (size_t)b * 3072, g_q2 + (size_t)b * 768,
                     1024, 256, s_whi, s_wlo, s_wx, s_wy, s_wz, s_win);
    __syncthreads();
    fps_stage<false>(g_q2 + (size_t)b * 768, g_q3 + (size_t)b * 192,
                     256, 64, s_whi, s_wlo, s_wx, s_wy, s_wz, s_win);
}

// ---------------- fused ball query + layer-1 (per-batch) ---------------------
__global__ __launch_bounds__(256)
void k_ball_l1(const float* __restrict__ ext, int scode, int qcode,
               const float* __restrict__ W, int CIN, int C1, int Q, int N,
               float r2, int b0) {
    extern __shared__ float sm[];
    float* wdp = sm;                           // [C1*3]
    int* sidx = (int*)(sm + C1 * 3);           // [8][32]
    int tid = threadIdx.x;
    for (int t = tid; t < C1 * 3; t += 256)
        wdp[t] = W[(t / 3) * CIN + (t % 3)];
    __syncthreads();

    int wi = tid >> 5, lane = tid & 31;
    int q = blockIdx.x * 8 + wi;
    if (q >= Q) return;
    const int b = b0;
    long long Nn = (long long)Q * 32;

    const float* qp = fbufc(qcode, nullptr) + b * bhalf(qcode) + (size_t)q * 3;
    float qx = qp[0], qy = qp[1], qz = qp[2];
    const float* sp = (scode < 0) ? ext + (size_t)b * N * 3
                                  : fbufc(scode, nullptr) + b * bhalf(scode);
    int* o = sidx + wi * 32;

    int cnt = 0, first = 0;
    for (int base = 0; base < N; base += 128) {    // N % 128 == 0 always
        float d2v[4];
#pragma unroll
        for (int j = 0; j < 4; ++j) {
            int i = base + j * 32 + lane;
            float dx = __fsub_rn(qx, __ldg(sp + i * 3 + 0));
            float dy = __fsub_rn(qy, __ldg(sp + i * 3 + 1));
            float dz = __fsub_rn(qz, __ldg(sp + i * 3 + 2));
            d2v[j] = d2_exact(dx, dy, dz);
        }
#pragma unroll
        for (int j = 0; j < 4; ++j) {
            bool hit = d2v[j] < r2;
            unsigned m = __ballot_sync(0xffffffffu, hit);
            if (cnt == 0 && m) first = base + j * 32 + __ffs(m) - 1;
            if (hit) {
                int pos = cnt + __popc(m & ((1u << lane) - 1u));
                if (pos < 32) o[pos] = base + j * 32 + lane;
            }
            cnt += __popc(m);
        }
        if (cnt >= 32) break;
    }
    for (int pos = cnt + lane; pos < 32; pos += 32) o[pos] = first;
    __syncwarp();

    int idx = o[lane];
    const float* spp = sp + (size_t)idx * 3;
    float dx = __fsub_rn(spp[0], qx);
    float dy = __fsub_rn(spp[1], qy);
    float dz = __fsub_rn(spp[2], qz);

    const float* Pb = g_P + b * 2097152u + idx;
    float* oh = g_h1 + b * 8388608u + (size_t)q * 32 + lane;
#pragma unroll 8
    for (int c = 0; c < C1; ++c) {
        float v = __ldg(Pb + (size_t)c * N);
        v = fmaf(wdp[c * 3 + 0], dx,
            fmaf(wdp[c * 3 + 1], dy,
            fmaf(wdp[c * 3 + 2], dz, v)));
        oh[(size_t)c * Nn] = v > 0.f ? v : 0.f;
    }
}

// ---------------- GEMM: Y = act(W @ X + bias), optional fused max-pool ------
template <int BM, int BK, int TM, bool POOL, bool RELU, bool GUARD>
__global__ __launch_bounds__(256, 2)
void k_gemm(const float* __restrict__ Wt, const float* __restrict__ bias,
            int xcode, int ycode, float* yext, int M, int K, int ldw,
            long long Nn, int b0) {
    __shared__ __align__(16) float As[2][BK][BM];
    __shared__ __align__(16) float Bs[2][BK][128];
    int b = blockIdx.z + b0;
    const float* X = fbufc(xcode, nullptr) + b * bhalf(xcode);
    int tid = threadIdx.x;
    int tm = tid >> 4, tn = tid & 15;
    int rowBase = blockIdx.y * BM;
    long long colBase = (long long)blockIdx.x * 128;

    float acc[TM][8];
#pragma unroll
    for (int i = 0; i < TM; ++i)
#pragma unroll
        for (int j = 0; j < 8; ++j) acc[i][j] = 0.f;

    if (GUARD) {
        for (int k0 = 0; k0 < K; k0 += BK) {
#pragma unroll
            for (int t = tid; t < BM * BK; t += 256) {
                int m = t / BK, kk = t % BK;
                As[0][kk][m] = (k0 + kk < K)
                    ? Wt[(size_t)(rowBase + m) * ldw + k0 + kk] : 0.f;
            }
#pragma unroll
            for (int t = tid; t < BK * 128; t += 256) {
                int kk = t >> 7, nn = t & 127;
                Bs[0][kk][nn] = (k0 + kk < K)
                    ? X[(size_t)(k0 + kk) * Nn + colBase + nn] : 0.f;
            }
            __syncthreads();
#pragma unroll
            for (int kk = 0; kk < BK; ++kk) {
                float a[TM], bb[8];
#pragma unroll
                for (int v = 0; v < TM / 4; ++v) {
                    float4 a4 = *reinterpret_cast<const float4*>(&As[0][kk][tm * TM + 4 * v]);
                    a[4 * v] = a4.x; a[4 * v + 1] = a4.y;
                    a[4 * v + 2] = a4.z; a[4 * v + 3] = a4.w;
                }
                float4 b0v = *reinterpret_cast<const float4*>(&Bs[0][kk][tn * 8]);
                float4 b1v = *reinterpret_cast<const float4*>(&Bs[0][kk][tn * 8 + 4]);
                bb[0] = b0v.x; bb[1] = b0v.y; bb[2] = b0v.z; bb[3] = b0v.w;
                bb[4] = b1v.x; bb[5] = b1v.y; bb[6] = b1v.z; bb[7] = b1v.w;
#pragma unroll
                for (int i = 0; i < TM; ++i)
#pragma unroll
                    for (int j = 0; j < 8; ++j)
                        acc[i][j] = fmaf(a[i], bb[j], acc[i][j]);
            }
            __syncthreads();
        }
    } else {
        constexpr int APT = BM * BK / 256;
        constexpr int TPR = BK / APT;
        constexpr int BQ = BK / 8;
        const int a_m = tid / TPR;
        const int a_k = (tid % TPR) * APT;
        const int b_k = tid >> 5;
        const int b_c = (tid & 31) * 4;

        const float* Arow = Wt + (size_t)(rowBase + a_m) * ldw + a_k;
        const float* Bcol = X + colBase + b_c;

        float ra[APT];
        float4 rb[BQ];
#pragma unroll
        for (int i = 0; i < APT; ++i) As[0][a_k + i][a_m] = Arow[i];
#pragma unroll
        for (int v = 0; v < BQ; ++v) {
            int kk = b_k + v * 8;
            *(float4*)&Bs[0][kk][b_c] = *(const float4*)(Bcol + (size_t)kk * Nn);
        }
        __syncthreads();

        const int ntiles = K / BK;
        for (int t = 0; t < ntiles; ++t) {
            int cur = t & 1;
            if (t + 1 < ntiles) {
                const float* An = Arow + (t + 1) * BK;
#pragma unroll
                for (int i = 0; i < APT; ++i) ra[i] = An[i];
#pragma unroll
                for (int v = 0; v < BQ; ++v) {
                    int kk = b_k + v * 8;
                    rb[v] = *(const float4*)(Bcol + (size_t)((t + 1) * BK + kk) * Nn);
                }
            }
#pragma unroll
            for (int kk = 0; kk < BK; ++kk) {
                float a[TM], bb[8];
#pragma unroll
                for (int v = 0; v < TM / 4; ++v) {
                    float4 a4 = *reinterpret_cast<const float4*>(&As[cur][kk][tm * TM + 4 * v]);
                    a[4 * v] = a4.x; a[4 * v + 1] = a4.y;
                    a[4 * v + 2] = a4.z; a[4 * v + 3] = a4.w;
                }
                float4 b0v = *reinterpret_cast<const float4*>(&Bs[cur][kk][tn * 8]);
                float4 b1v = *reinterpret_cast<const float4*>(&Bs[cur][kk][tn * 8 + 4]);
                bb[0] = b0v.x; bb[1] = b0v.y; bb[2] = b0v.z; bb[3] = b0v.w;
                bb[4] = b1v.x; bb[5] = b1v.y; bb[6] = b1v.z; bb[7] = b1v.w;
#pragma unroll
                for (int i = 0; i < TM; ++i)
#pragma unroll
                    for (int j = 0; j < 8; ++j)
                        acc[i][j] = fmaf(a[i], bb[j], acc[i][j]);
            }
            if (t + 1 < ntiles) {
                int nxt = cur ^ 1;
#pragma unroll
                for (int i = 0; i < APT; ++i) As[nxt][a_k + i][a_m] = ra[i];
#pragma unroll
                for (int v = 0; v < BQ; ++v)
                    *(float4*)&Bs[nxt][b_k + v * 8][b_c] = rb[v];
            }
            __syncthreads();
        }
    }

    if (!POOL) {
        float* Y = fbufw(ycode, nullptr) + b * bhalf(ycode);
#pragma unroll
        for (int i = 0; i < TM; ++i) {
            int row = rowBase + tm * TM + i;
            float bv = bias[row];
            float* yr = Y + (size_t)row * Nn + colBase + tn * 8;
#pragma unroll
            for (int j = 0; j < 8; ++j) {
                float v = acc[i][j] + bv;
                yr[j] = RELU ? (v > 0.f ? v : 0.f) : v;
            }
        }
    } else {
        long long Q = Nn >> 5;
        float* Y = (ycode < 0) ? yext + (size_t)b * M * Q
                               : fbufw(ycode, nullptr) + b * bhalf(ycode);
#pragma unroll
        for (int i = 0; i < TM; ++i) {
            float m = acc[i][0];
#pragma unroll
            for (int j = 1; j < 8; ++j) m = fmaxf(m, acc[i][j]);
            m = fmaxf(m, __shfl_xor_sync(0xffffffffu, m, 1));
            m = fmaxf(m, __shfl_xor_sync(0xffffffffu, m, 2));
            if ((tn & 3) == 0) {
                int row = rowBase + tm * TM + i;
                float v = m + bias[row];
                long long q = (colBase >> 5) + (tn >> 2);
                Y[(size_t)row * Q + q] = v > 0.f ? v : 0.f;
            }
        }
    }
}

// ---------------- stream/event handles (created at load, before harness) ----
struct HxStreams {
    cudaStream_t s2, s4;
    cudaEvent_t evT, evA, evP, evB1, evB2, evD;
    bool ok;
    HxStreams() {
        ok = cudaStreamCreateWithFlags(&s2, cudaStreamNonBlocking) == cudaSuccess
          && cudaStreamCreateWithFlags(&s4, cudaStreamNonBlocking) == cudaSuccess
          && cudaEventCreateWithFlags(&evT, cudaEventDisableTiming) == cudaSuccess
          && cudaEventCreateWithFlags(&evA, cudaEventDisableTiming) == cudaSuccess
          && cudaEventCreateWithFlags(&evP, cudaEventDisableTiming) == cudaSuccess
          && cudaEventCreateWithFlags(&evB1, cudaEventDisableTiming) == cudaSuccess
          && cudaEventCreateWithFlags(&evB2, cudaEventDisableTiming) == cudaSuccess
          && cudaEventCreateWithFlags(&evD, cudaEventDisableTiming) == cudaSuccess;
    }
};
static HxStreams g_hx;

// ---------------------------------------------------------------------------
extern "C" void kernel_launch(void* const* d_in, const int* in_sizes, int n_in,
                              void* d_out, int out_size) {
    (void)in_sizes; (void)n_in; (void)out_size;
    const float* xyz = (const float*)d_in[0];
    const float* W[4][3]; const float* BV[4][3];
    {
        int p = 1;
        for (int k = 0; k < 4; ++k)
            for (int l = 0; l < 3; ++l) {
                W[k][l]  = (const float*)d_in[p++];
                BV[k][l] = (const float*)d_in[p++];
            }
    }

    static const int   Ns[4]  = {16384, 4096, 1024, 256};
    static const int   CIN[4] = {6, 131, 259, 515};
    static const int   C1[4]  = {64, 128, 256, 512};
    static const int   C2[4]  = {64, 128, 256, 512};
    static const int   C3[4]  = {128, 256, 512, 1024};
    static const float R2[4]  = {(float)(0.1 * 0.1), (float)(0.2 * 0.2),
                                 (float)(0.4 * 0.4), (float)(0.8 * 0.8)};
    static const int supc[4] = {-1, 6, 7, 8};   // support xyz buffer
    static const int qc[4]   = {6, 7, 8, 9};    // query   xyz buffer
    static const int fic[4]  = {5, 3, 4, 3};    // feats-in buffer
    static const int foc[4]  = {3, 4, 3, -1};   // pooled feats-out

    auto gemm = [&](cudaStream_t st, const float* Wp, const float* bp,
                    int xc, int yc, float* ye, int M, int K, int ldw,
                    long long Nn, bool pool, bool relu, int b0, int zdim) {
        bool guard = (K % 16) != 0;
        if (M >= 128) {
            dim3 g((unsigned)(Nn / 128), M / 128, zdim);
            if (guard) {
                if (pool) k_gemm<128, 16, 8, true,  true,  true ><<<g, 256, 0, st>>>(Wp, bp, xc, yc, ye, M, K, ldw, Nn, b0);
                else if (relu) k_gemm<128, 16, 8, false, true,  true ><<<g, 256, 0, st>>>(Wp, bp, xc, yc, ye, M, K, ldw, Nn, b0);
                else k_gemm<128, 16, 8, false, false, true ><<<g, 256, 0, st>>>(Wp, bp, xc, yc, ye, M, K, ldw, Nn, b0);
            } else {
                if (pool) k_gemm<128, 16, 8, true,  true,  false><<<g, 256, 0, st>>>(Wp, bp, xc, yc, ye, M, K, ldw, Nn, b0);
                else if (relu) k_gemm<128, 16, 8, false, true,  false><<<g, 256, 0, st>>>(Wp, bp, xc, yc, ye, M, K, ldw, Nn, b0);
                else k_gemm<128, 16, 8, false, false, false><<<g, 256, 0, st>>>(Wp, bp, xc, yc, ye, M, K, ldw, Nn, b0);
            }
        } else {
            dim3 g((unsigned)(Nn / 128), M / 64, zdim);
            if (guard) {
                if (pool) k_gemm<64, 16, 4, true,  true,  true ><<<g, 256, 0, st>>>(Wp, bp, xc, yc, ye, M, K, ldw, Nn, b0);
                else if (relu) k_gemm<64, 16, 4, false, true,  true ><<<g, 256, 0, st>>>(Wp, bp, xc, yc, ye, M, K, ldw, Nn, b0);
                else k_gemm<64, 16, 4, false, false, true ><<<g, 256, 0, st>>>(Wp, bp, xc, yc, ye, M, K, ldw, Nn, b0);
            } else {
                if (pool) k_gemm<64, 16, 4, true,  true,  false><<<g, 256, 0, st>>>(Wp, bp, xc, yc, ye, M, K, ldw, Nn, b0);
                else if (relu) k_gemm<64, 16, 4, false, true,  false><<<g, 256, 0, st>>>(Wp, bp, xc, yc, ye, M, K, ldw, Nn, b0);
                else k_gemm<64, 16, 4, false, false, false><<<g, 256, 0, st>>>(Wp, bp, xc, yc, ye, M, K, ldw, Nn, b0);
            }
        }
    };

    auto ball = [&](cudaStream_t st, int k, int b) {
        int N = Ns[k], Q = N / 4;
        size_t smem = (size_t)C1[k] * 3 * 4 + 8 * 32 * 4;
        k_ball_l1<<<Q / 8, 256, smem, st>>>(
            xyz, supc[k], qc[k], W[k][0], CIN[k], C1[k], Q, N, R2[k], b);
    };

    // per-batch stage chain (stages 0..3); P0 must already be done.
    auto chain = [&](cudaStream_t sb, int b, bool ov) {
        for (int k = 0; k < 4; ++k) {
            int N = Ns[k], Q = N / 4;
            long long Nn = (long long)Q * 32;
            if (k >= 1)
                gemm(sb, W[k][0] + 3, BV[k][0], fic[k], 0, nullptr,
                     C1[k], CIN[k] - 3, CIN[k], (long long)N, false, false, b, 1);
            if (k == 1 && ov) cudaStreamWaitEvent(sb, g_hx.evB1, 0);  // q1 ready
            if (k == 2 && ov) cudaStreamWaitEvent(sb, g_hx.evB2, 0);  // q2/q3 ready
            ball(sb, k, b);
            gemm(sb, W[k][1], BV[k][1], 1, 2, nullptr,
                 C2[k], C1[k], C1[k], Nn, false, true, b, 1);
            gemm(sb, W[k][2], BV[k][2], 2, foc[k], (float*)d_out,
                 C3[k], C2[k], C2[k], Nn, true, true, b, 1);
        }
    };

    const bool ov = g_hx.ok;

    if (ov) {
        cudaStream_t s2 = g_hx.s2, s4 = g_hx.s4;
        // s0: transpose -> evT -> FPS0 (alone on the chip) -> evA
        k_transpose<<<(2 * 16384 + 255) / 256, 256>>>(xyz);
        cudaEventRecord(g_hx.evT, 0);
        k_fps_cl<<<16, 512>>>(xyz, 16384, 4096);
        cudaEventRecord(g_hx.evA, 0);
        // s2: P0 (both batches, tiny) under FPS0; then stage-1 FPS -> evB1,
        // stages 2-3 -> evB2 (single-CTA kernels; cluster FPS only for stage 0)
        cudaStreamWaitEvent(s2, g_hx.evT, 0);
        gemm(s2, W[0][0] + 3, BV[0][0], fic[0], 0, nullptr,
             C1[0], CIN[0] - 3, CIN[0], 16384LL, false, false, 0, 2);
        cudaEventRecord(g_hx.evP, s2);
        cudaStreamWaitEvent(s2, g_hx.evA, 0);
        k_fps_s1<<<2, 1024, 0, s2>>>();
        cudaEventRecord(g_hx.evB1, s2);
        k_fps_s23<<<2, 1024, 0, s2>>>();
        cudaEventRecord(g_hx.evB2, s2);
        // batch 0 chain on s0 (after fps_cl in program order; needs P0)
        cudaStreamWaitEvent(0, g_hx.evP, 0);
        // batch 1 chain on s4 (fork via in-graph events evA + evP)
        cudaStreamWaitEvent(s4, g_hx.evA, 0);
        cudaStreamWaitEvent(s4, g_hx.evP, 0);
        chain(s4, 1, true);
        cudaEventRecord(g_hx.evD, s4);
        chain(0, 0, true);
        cudaStreamWaitEvent(0, g_hx.evD, 0);             // join batch-1 chain
    } else {
        // sequential fallback
        k_transpose<<<(2 * 16384 + 255) / 256, 256>>>(xyz);
        k_fps_cl<<<16, 512>>>(xyz, 16384, 4096);
        k_fps_s1<<<2, 1024>>>();
        k_fps_s23<<<2, 1024>>>();
        gemm(0, W[0][0] + 3, BV[0][0], fic[0], 0, nullptr,
             C1[0], CIN[0] - 3, CIN[0], 16384LL, false, false, 0, 2);
        for (int k = 0; k < 4; ++k) {
            int N = Ns[k], Q = N / 4;
            long long Nn = (long long)Q * 32;
            if (k >= 1)
                gemm(0, W[k][0] + 3, BV[k][0], fic[k], 0, nullptr,
                     C1[k], CIN[k] - 3, CIN[k], (long long)N, false, false, 0, 2);
            ball(0, k, 0);
            ball(0, k, 1);
            gemm(0, W[k][1], BV[k][1], 1, 2, nullptr,
                 C2[k], C1[k], C1[k], Nn, false, true, 0, 2);
            gemm(0, W[k][2], BV[k][2], 2, foc[k], (float*)d_out,
                 C3[k], C2[k], C2[k], Nn, true, true, 0, 2);
        }
    }
}

// round 17
// speedup vs baseline: 1.0690x; 1.0036x over previous
#include <cuda_runtime.h>
#include <cuda_bf16.h>
#include <cooperative_groups.h>

namespace cg = cooperative_groups;
typedef unsigned long long u64;

// ---------------------------------------------------------------------------
// PointNet++ encoder, B=2, N=16384, 4 SA stages (stride 4, nsample 32)
// ---------------------------------------------------------------------------

// ---------------- scratch buffers (device globals; no allocs allowed) ------
// Internal buffers use FIXED per-batch half strides (bhalf) so the two batch
// pipelines can be at different stages concurrently without overlap.
__device__ float g_P[4194304];     // projected feats P   half = 2097152
__device__ float g_h1[16777216];   // layer-1 out         half = 8388608
__device__ float g_h2[16777216];   // layer-2 out         half = 8388608
__device__ float g_fA[1048576];    // pooled feats ping   half = 524288
__device__ float g_fB[1048576];    // pooled feats pong   half = 524288
__device__ float g_feats0[98304];  // xyz^T (SoA)         half = 49152
__device__ float g_q0[24576];      // stage0 query xyz    half = 12288
__device__ float g_q1[6144];       // stage1 query xyz    half = 3072
__device__ float g_q2[1536];       // stage2 query xyz    half = 768
__device__ float g_q3[384];        // stage3 query xyz    half = 192

__device__ __forceinline__ const float* fbufc(int code, const float* ext) {
    switch (code) {
        case 0: return g_P;   case 1: return g_h1;  case 2: return g_h2;
        case 3: return g_fA;  case 4: return g_fB;  case 5: return g_feats0;
        case 6: return g_q0;  case 7: return g_q1;  case 8: return g_q2;
        case 9: return g_q3;  default: return ext;
    }
}
__device__ __forceinline__ float* fbufw(int code, float* ext) {
    switch (code) {
        case 0: return g_P;   case 1: return g_h1;  case 2: return g_h2;
        case 3: return g_fA;  case 4: return g_fB;  case 5: return g_feats0;
        case 6: return g_q0;  case 7: return g_q1;  case 8: return g_q2;
        case 9: return g_q3;  default: return ext;
    }
}
__device__ __forceinline__ size_t bhalf(int code) {
    switch (code) {
        case 0: return 2097152u;  case 1: return 8388608u; case 2: return 8388608u;
        case 3: return 524288u;   case 4: return 524288u;  case 5: return 49152u;
        case 6: return 12288u;    case 7: return 3072u;    case 8: return 768u;
        case 9: return 192u;      default: return 0u;
    }
}

// d2 exactly as JAX computes it: ((dx*dx + dy*dy) + dz*dz), no FMA contraction
__device__ __forceinline__ float d2_exact(float dx, float dy, float dz) {
    return __fadd_rn(__fadd_rn(__fmul_rn(dx, dx), __fmul_rn(dy, dy)),
                     __fmul_rn(dz, dz));
}

// ---- packed f32x2 helpers (rn mul/add: per-lane bit-identical to scalar) ---
__device__ __forceinline__ u64 pack2(float lo, float hi) {
    u64 r; asm("mov.b64 %0,{%1,%2};" : "=l"(r) : "f"(lo), "f"(hi)); return r;
}
__device__ __forceinline__ void unpack2(u64 v, float& lo, float& hi) {
    asm("mov.b64 {%0,%1},%2;" : "=f"(lo), "=f"(hi) : "l"(v));
}
__device__ __forceinline__ u64 add2(u64 a, u64 b) {
    u64 r; asm("add.rn.f32x2 %0,%1,%2;" : "=l"(r) : "l"(a), "l"(b)); return r;
}
__device__ __forceinline__ u64 mul2(u64 a, u64 b) {
    u64 r; asm("mul.rn.f32x2 %0,%1,%2;" : "=l"(r) : "l"(a), "l"(b)); return r;
}

// ---------------- feats0 = xyz^T  [B,3,N] -----------------------------------
__global__ void k_transpose(const float* __restrict__ xyz) {
    int i = blockIdx.x * blockDim.x + threadIdx.x;
    if (i >= 2 * 16384) return;
    int b = i >> 14, n = i & 16383;
#pragma unroll
    for (int c = 0; c < 3; ++c)
        g_feats0[b * 49152 + c * 16384 + n] = xyz[(size_t)i * 3 + c];
}

// ---------------- FPS stage 0: 8-CTA cluster per batch (N=16384) ------------
struct __align__(16) SlotA { u64 key; float x, y; };

__global__ __cluster_dims__(8, 1, 1) __launch_bounds__(512, 1)
void k_fps_cl(const float* __restrict__ xyz, int N, int npoint) {
    cg::cluster_group cluster = cg::this_cluster();
    const int rank = cluster.block_rank();
    const int b = blockIdx.x >> 3;
    const int tid = threadIdx.x;
    const int gbase = rank * (N >> 3);        // 2048 pts per CTA

    __shared__ unsigned s_whi[16], s_wlo[16];
    __shared__ float s_wx[16], s_wy[16], s_wz[16];
    __shared__ SlotA s_sa[2][8];              // [parity][src rank]
    __shared__ float s_sz[2][8];
    __shared__ __align__(8) u64 s_mbar;

    const float* base = xyz + (size_t)b * N * 3;

    u64 px01, px23, py01, py23, pz01, pz23;
    float pxs[4], pys[4], pzs[4], md[4];
    {
#pragma unroll
        for (int j = 0; j < 4; ++j) {
            const float* p = base + (size_t)(gbase + tid + j * 512) * 3;
            pxs[j] = p[0]; pys[j] = p[1]; pzs[j] = p[2];
            md[j] = 1e10f;
        }
        px01 = pack2(pxs[0], pxs[1]); px23 = pack2(pxs[2], pxs[3]);
        py01 = pack2(pys[0], pys[1]); py23 = pack2(pys[2], pys[3]);
        pz01 = pack2(pzs[0], pzs[1]); pz23 = pack2(pzs[2], pzs[3]);
    }

    unsigned mbar32 = (unsigned)__cvta_generic_to_shared(&s_mbar);
    if (tid == 0)
        asm volatile("mbarrier.init.shared.b64 [%0], %1;"
                     :: "r"(mbar32), "r"(8) : "memory");

    float* qb = g_q0 + (size_t)b * 12288;
    float lx = base[0], ly = base[1], lz = base[2];
    if (rank == 0 && tid == 0) { qb[0] = lx; qb[1] = ly; qb[2] = lz; }
    cluster.sync();                            // mbarriers + slots live

    int par = 0;
    unsigned phase = 0;
    for (int it = 1; it < npoint; ++it) {
        u64 nlx2 = pack2(-lx, -lx), nly2 = pack2(-ly, -ly), nlz2 = pack2(-lz, -lz);
        float d0, d1, d2, d3;
        {
            u64 dx = add2(px01, nlx2), dy = add2(py01, nly2), dz = add2(pz01, nlz2);
            u64 s = add2(add2(mul2(dx, dx), mul2(dy, dy)), mul2(dz, dz));
            unpack2(s, d0, d1);
        }
        {
            u64 dx = add2(px23, nlx2), dy = add2(py23, nly2), dz = add2(pz23, nlz2);
            u64 s = add2(add2(mul2(dx, dx), mul2(dy, dy)), mul2(dz, dz));
            unpack2(s, d2, d3);
        }
        float m, bm; int bj;
        m = fminf(md[0], d0); md[0] = m; bm = m; bj = 0;
        m = fminf(md[1], d1); md[1] = m; if (m > bm) { bm = m; bj = 1; }
        m = fminf(md[2], d2); md[2] = m; if (m > bm) { bm = m; bj = 2; }
        m = fminf(md[3], d3); md[3] = m; if (m > bm) { bm = m; bj = 3; }

        unsigned hi = __float_as_uint(bm);
        unsigned lo = 0xFFFFFFFFu - (unsigned)(gbase + tid + bj * 512);
        unsigned m1 = __reduce_max_sync(0xffffffffu, hi);
        unsigned cnd = (hi == m1) ? lo : 0u;
        unsigned m2 = __reduce_max_sync(0xffffffffu, cnd);
        if (hi == m1 && lo == m2) {            // unique (indices unique)
            int w = tid >> 5;
            s_whi[w] = m1; s_wlo[w] = m2;
            s_wx[w] = pxs[bj]; s_wy[w] = pys[bj]; s_wz[w] = pzs[bj];
        }
        __syncthreads();
        if (tid < 32) {
            unsigned hi2 = (tid < 16) ? s_whi[tid] : 0u;
            unsigned lo2 = (tid < 16) ? s_wlo[tid] : 0u;
            unsigned M1 = __reduce_max_sync(0xffffffffu, hi2);
            unsigned c2 = (hi2 == M1) ? lo2 : 0u;
            unsigned M2 = __reduce_max_sync(0xffffffffu, c2);
            unsigned mb = __ballot_sync(0xffffffffu,
                                        (tid < 16) && hi2 == M1 && lo2 == M2);
            int wl = __ffs(mb) - 1;
            float x2 = __shfl_sync(0xffffffffu, s_wx[tid & 15], wl);
            float y2 = __shfl_sync(0xffffffffu, s_wy[tid & 15], wl);
            float z2 = __shfl_sync(0xffffffffu, s_wz[tid & 15], wl);
            if (tid < 8) {
                uint4 v; v.x = M2; v.y = M1;
                v.z = __float_as_uint(x2); v.w = __float_as_uint(y2);
                *(uint4*)cluster.map_shared_rank((void*)&s_sa[par][rank], tid) = v;
                *(float*)cluster.map_shared_rank((void*)&s_sz[par][rank], tid) = z2;
                unsigned ra;
                asm volatile("mapa.shared::cluster.u32 %0, %1, %2;"
                             : "=r"(ra) : "r"(mbar32), "r"(tid));
                asm volatile(
                    "mbarrier.arrive.release.cluster.shared::cluster.b64 _, [%0];"
                    :: "r"(ra) : "memory");
            }
            unsigned done = 0;
            while (!done) {
                asm volatile(
                    "{\n\t.reg .pred p;\n\t"
                    "mbarrier.try_wait.parity.acquire.cluster.shared::cta.b64 "
                    "p, [%1], %2, 0x989680;\n\t"
                    "selp.b32 %0, 1, 0, p;\n\t}"
                    : "=r"(done) : "r"(mbar32), "r"(phase) : "memory");
            }
        }
        __syncthreads();                       // releases all warps, orders smem
        {
            u64 bk = s_sa[par][0].key;
            int bs = 0;
#pragma unroll
            for (int s = 1; s < 8; ++s) {
                u64 k = s_sa[par][s].key;
                if (k > bk) { bk = k; bs = s; }
            }
            lx = s_sa[par][bs].x; ly = s_sa[par][bs].y; lz = s_sz[par][bs];
            if (rank == 0 && tid == 0) {
                qb[it * 3 + 0] = lx; qb[it * 3 + 1] = ly; qb[it * 3 + 2] = lz;
            }
        }
        par ^= 1;
        phase ^= 1;
    }
    cluster.sync();
}

// ---------------- FPS stages 1-3: one CTA per batch --------------------------
template <bool FULL>
__device__ void fps_stage(const float* __restrict__ sup, float* __restrict__ qout,
                          int N, int npoint,
                          unsigned* s_whi, unsigned* s_wlo,
                          float* s_wx, float* s_wy, float* s_wz, float* s_win) {
    int tid = threadIdx.x;
    float px[4], py[4], pz[4], md[4];
#pragma unroll
    for (int j = 0; j < 4; ++j) {
        int i = tid + j * 1024;
        md[j] = 1e10f;
        if (FULL || i < N) {
            const float* p = sup + (size_t)i * 3;
            px[j] = p[0]; py[j] = p[1]; pz[j] = p[2];
        } else { px[j] = 0.f; py[j] = 0.f; pz[j] = 0.f; }
    }
    u64 px01, px23, py01, py23, pz01, pz23;
    if (FULL) {
        px01 = pack2(px[0], px[1]); px23 = pack2(px[2], px[3]);
        py01 = pack2(py[0], py[1]); py23 = pack2(py[2], py[3]);
        pz01 = pack2(pz[0], pz[1]); pz23 = pack2(pz[2], pz[3]);
    }
    float lx = sup[0], ly = sup[1], lz = sup[2];
    if (tid == 0) { qout[0] = lx; qout[1] = ly; qout[2] = lz; }
    bool valid = tid < N;

    for (int it = 1; it < npoint; ++it) {
        float bm = -1.f, bx = 0.f, by = 0.f, bz = 0.f;
        int bi = 0;
        if (FULL) {
            u64 nlx2 = pack2(-lx, -lx), nly2 = pack2(-ly, -ly), nlz2 = pack2(-lz, -lz);
            float d0, d1, d2, d3;
            {
                u64 dx = add2(px01, nlx2), dy = add2(py01, nly2), dz = add2(pz01, nlz2);
                u64 s = add2(add2(mul2(dx, dx), mul2(dy, dy)), mul2(dz, dz));
                unpack2(s, d0, d1);
            }
            {
                u64 dx = add2(px23, nlx2), dy = add2(py23, nly2), dz = add2(pz23, nlz2);
                u64 s = add2(add2(mul2(dx, dx), mul2(dy, dy)), mul2(dz, dz));
                unpack2(s, d2, d3);
            }
            float m; int bj;
            m = fminf(md[0], d0); md[0] = m; bm = m; bj = 0;
            m = fminf(md[1], d1); md[1] = m; if (m > bm) { bm = m; bj = 1; }
            m = fminf(md[2], d2); md[2] = m; if (m > bm) { bm = m; bj = 2; }
            m = fminf(md[3], d3); md[3] = m; if (m > bm) { bm = m; bj = 3; }
            bx = px[bj]; by = py[bj]; bz = pz[bj];
            bi = tid + bj * 1024;
        } else {
#pragma unroll
            for (int j = 0; j < 4; ++j) {
                int i = tid + j * 1024;
                if (i < N) {
                    float dx = __fsub_rn(px[j], lx);
                    float dy = __fsub_rn(py[j], ly);
                    float dz = __fsub_rn(pz[j], lz);
                    float d = d2_exact(dx, dy, dz);
                    float m = fminf(md[j], d);
                    md[j] = m;
                    bool p = m > bm;
                    bm = fmaxf(bm, m);
                    bx = p ? px[j] : bx; by = p ? py[j] : by; bz = p ? pz[j] : bz;
                    bi = p ? i : bi;
                }
            }
        }
        unsigned hi = valid ? __float_as_uint(bm) : 0u;
        unsigned lo = valid ? (0xFFFFFFFFu - (unsigned)bi)
                            : (0xFFFFFFFFu - (unsigned)(N + tid));
        unsigned m1 = __reduce_max_sync(0xffffffffu, hi);
        unsigned cnd = (hi == m1) ? lo : 0u;
        unsigned m2 = __reduce_max_sync(0xffffffffu, cnd);
        if (hi == m1 && lo == m2) {
            int w = tid >> 5;
            s_whi[w] = m1; s_wlo[w] = m2;
            s_wx[w] = bx; s_wy[w] = by; s_wz[w] = bz;
        }
        __syncthreads();
        if (tid < 32) {
            unsigned hi2 = s_whi[tid], lo2 = s_wlo[tid];
            unsigned M1 = __reduce_max_sync(0xffffffffu, hi2);
            unsigned c2 = (hi2 == M1) ? lo2 : 0u;
            unsigned M2 = __reduce_max_sync(0xffffffffu, c2);
            unsigned mb = __ballot_sync(0xffffffffu, hi2 == M1 && lo2 == M2);
            int wl = __ffs(mb) - 1;
            float x2 = __shfl_sync(0xffffffffu, s_wx[tid], wl);
            float y2 = __shfl_sync(0xffffffffu, s_wy[tid], wl);
            float z2 = __shfl_sync(0xffffffffu, s_wz[tid], wl);
            if (tid == 0) {
                s_win[0] = x2; s_win[1] = y2; s_win[2] = z2;
                qout[it * 3 + 0] = x2; qout[it * 3 + 1] = y2; qout[it * 3 + 2] = z2;
            }
        }
        __syncthreads();
        lx = s_win[0]; ly = s_win[1]; lz = s_win[2];
    }
}

__global__ __launch_bounds__(1024, 1)
void k_fps_s1() {
    __shared__ unsigned s_whi[32], s_wlo[32];
    __shared__ float s_wx[32], s_wy[32], s_wz[32], s_win[3];
    int b = blockIdx.x;
    fps_stage<true >(g_q0 + (size_t)b * 12288, g_q1 + (size_t)b * 3072,
                     4096, 1024, s_whi, s_wlo, s_wx, s_wy, s_wz, s_win);
}

__global__ __launch_bounds__(1024, 1)
void k_fps_s23() {
    __shared__ unsigned s_whi[32], s_wlo[32];
    __shared__ float s_wx[32], s_wy[32], s_wz[32], s_win[3];
    int b = blockIdx.x;
    fps_stage<false>(g_q1 + (size_t)b * 3072, g_q2 + (size_t)b * 768,
                     1024, 256, s_whi, s_wlo, s_wx, s_wy, s_wz, s_win);
    __syncthreads();
    fps_stage<false>(g_q2 + (size_t)b * 768, g_q3 + (size_t)b * 192,
                     256, 64, s_whi, s_wlo, s_wx, s_wy, s_wz, s_win);
}

// ---------------- fused ball query + layer-1 (per-batch) ---------------------
// scode < 0 (stage 0): scan g_feats0 SoA planes (3x fewer L1 wavefronts);
// otherwise scan the AoS q-buffer. Values are bit-identical either way.
__global__ __launch_bounds__(256)
void k_ball_l1(const float* __restrict__ ext, int scode, int qcode,
               const float* __restrict__ W, int CIN, int C1, int Q, int N,
               float r2, int b0) {
    extern __shared__ float sm[];
    float* wdp = sm;                           // [C1*3]
    int* sidx = (int*)(sm + C1 * 3);           // [8][32]
    int tid = threadIdx.x;
    for (int t = tid; t < C1 * 3; t += 256)
        wdp[t] = W[(t / 3) * CIN + (t % 3)];
    __syncthreads();

    int wi = tid >> 5, lane = tid & 31;
    int q = blockIdx.x * 8 + wi;
    if (q >= Q) return;
    const int b = b0;
    long long Nn = (long long)Q * 32;
    const bool soa = (scode < 0);

    const float* qp = fbufc(qcode, nullptr) + b * bhalf(qcode) + (size_t)q * 3;
    float qx = qp[0], qy = qp[1], qz = qp[2];
    const float* sp = nullptr;
    const float *sxp = nullptr, *syp = nullptr, *szp = nullptr;
    if (soa) {
        const float* pl = g_feats0 + b * 49152u;
        sxp = pl; syp = pl + 16384; szp = pl + 2 * 16384;
    } else {
        sp = fbufc(scode, nullptr) + b * bhalf(scode);
    }
    int* o = sidx + wi * 32;

    int cnt = 0, first = 0;
    for (int base = 0; base < N; base += 128) {    // N % 128 == 0 always
        float d2v[4];
        if (soa) {
#pragma unroll
            for (int j = 0; j < 4; ++j) {
                int i = base + j * 32 + lane;
                float dx = __fsub_rn(qx, __ldg(sxp + i));
                float dy = __fsub_rn(qy, __ldg(syp + i));
                float dz = __fsub_rn(qz, __ldg(szp + i));
                d2v[j] = d2_exact(dx, dy, dz);
            }
        } else {
#pragma unroll
            for (int j = 0; j < 4; ++j) {
                int i = base + j * 32 + lane;
                float dx = __fsub_rn(qx, __ldg(sp + i * 3 + 0));
                float dy = __fsub_rn(qy, __ldg(sp + i * 3 + 1));
                float dz = __fsub_rn(qz, __ldg(sp + i * 3 + 2));
                d2v[j] = d2_exact(dx, dy, dz);
            }
        }
#pragma unroll
        for (int j = 0; j < 4; ++j) {
            bool hit = d2v[j] < r2;
            unsigned m = __ballot_sync(0xffffffffu, hit);
            if (cnt == 0 && m) first = base + j * 32 + __ffs(m) - 1;
            if (hit) {
                int pos = cnt + __popc(m & ((1u << lane) - 1u));
                if (pos < 32) o[pos] = base + j * 32 + lane;
            }
            cnt += __popc(m);
        }
        if (cnt >= 32) break;
    }
    for (int pos = cnt + lane; pos < 32; pos += 32) o[pos] = first;
    __syncwarp();

    int idx = o[lane];
    float dx, dy, dz;
    if (soa) {
        dx = __fsub_rn(sxp[idx], qx);
        dy = __fsub_rn(syp[idx], qy);
        dz = __fsub_rn(szp[idx], qz);
    } else {
        const float* spp = sp + (size_t)idx * 3;
        dx = __fsub_rn(spp[0], qx);
        dy = __fsub_rn(spp[1], qy);
        dz = __fsub_rn(spp[2], qz);
    }

    const float* Pb = g_P + b * 2097152u + idx;
    float* oh = g_h1 + b * 8388608u + (size_t)q * 32 + lane;
#pragma unroll 8
    for (int c = 0; c < C1; ++c) {
        float v = __ldg(Pb + (size_t)c * N);
        v = fmaf(wdp[c * 3 + 0], dx,
            fmaf(wdp[c * 3 + 1], dy,
            fmaf(wdp[c * 3 + 2], dz, v)));
        oh[(size_t)c * Nn] = v > 0.f ? v : 0.f;
    }
}

// ---------------- GEMM: Y = act(W @ X + bias), optional fused max-pool ------
template <int BM, int BK, int TM, bool POOL, bool RELU, bool GUARD>
__global__ __launch_bounds__(256, 2)
void k_gemm(const float* __restrict__ Wt, const float* __restrict__ bias,
            int xcode, int ycode, float* yext, int M, int K, int ldw,
            long long Nn, int b0) {
    __shared__ __align__(16) float As[2][BK][BM];
    __shared__ __align__(16) float Bs[2][BK][128];
    int b = blockIdx.z + b0;
    const float* X = fbufc(xcode, nullptr) + b * bhalf(xcode);
    int tid = threadIdx.x;
    int tm = tid >> 4, tn = tid & 15;
    int rowBase = blockIdx.y * BM;
    long long colBase = (long long)blockIdx.x * 128;

    float acc[TM][8];
#pragma unroll
    for (int i = 0; i < TM; ++i)
#pragma unroll
        for (int j = 0; j < 8; ++j) acc[i][j] = 0.f;

    if (GUARD) {
        for (int k0 = 0; k0 < K; k0 += BK) {
#pragma unroll
            for (int t = tid; t < BM * BK; t += 256) {
                int m = t / BK, kk = t % BK;
                As[0][kk][m] = (k0 + kk < K)
                    ? Wt[(size_t)(rowBase + m) * ldw + k0 + kk] : 0.f;
            }
#pragma unroll
            for (int t = tid; t < BK * 128; t += 256) {
                int kk = t >> 7, nn = t & 127;
                Bs[0][kk][nn] = (k0 + kk < K)
                    ? X[(size_t)(k0 + kk) * Nn + colBase + nn] : 0.f;
            }
            __syncthreads();
#pragma unroll
            for (int kk = 0; kk < BK; ++kk) {
                float a[TM], bb[8];
#pragma unroll
                for (int v = 0; v < TM / 4; ++v) {
                    float4 a4 = *reinterpret_cast<const float4*>(&As[0][kk][tm * TM + 4 * v]);
                    a[4 * v] = a4.x; a[4 * v + 1] = a4.y;
                    a[4 * v + 2] = a4.z; a[4 * v + 3] = a4.w;
                }
                float4 b0v = *reinterpret_cast<const float4*>(&Bs[0][kk][tn * 8]);
                float4 b1v = *reinterpret_cast<const float4*>(&Bs[0][kk][tn * 8 + 4]);
                bb[0] = b0v.x; bb[1] = b0v.y; bb[2] = b0v.z; bb[3] = b0v.w;
                bb[4] = b1v.x; bb[5] = b1v.y; bb[6] = b1v.z; bb[7] = b1v.w;
#pragma unroll
                for (int i = 0; i < TM; ++i)
#pragma unroll
                    for (int j = 0; j < 8; ++j)
                        acc[i][j] = fmaf(a[i], bb[j], acc[i][j]);
            }
            __syncthreads();
        }
    } else {
        constexpr int APT = BM * BK / 256;
        constexpr int TPR = BK / APT;
        constexpr int BQ = BK / 8;
        const int a_m = tid / TPR;
        const int a_k = (tid % TPR) * APT;
        const int b_k = tid >> 5;
        const int b_c = (tid & 31) * 4;

        const float* Arow = Wt + (size_t)(rowBase + a_m) * ldw + a_k;
        const float* Bcol = X + colBase + b_c;

        float ra[APT];
        float4 rb[BQ];
#pragma unroll
        for (int i = 0; i < APT; ++i) As[0][a_k + i][a_m] = Arow[i];
#pragma unroll
        for (int v = 0; v < BQ; ++v) {
            int kk = b_k + v * 8;
            *(float4*)&Bs[0][kk][b_c] = *(const float4*)(Bcol + (size_t)kk * Nn);
        }
        __syncthreads();

        const int ntiles = K / BK;
        for (int t = 0; t < ntiles; ++t) {
            int cur = t & 1;
            if (t + 1 < ntiles) {
                const float* An = Arow + (t + 1) * BK;
#pragma unroll
                for (int i = 0; i < APT; ++i) ra[i] = An[i];
#pragma unroll
                for (int v = 0; v < BQ; ++v) {
                    int kk = b_k + v * 8;
                    rb[v] = *(const float4*)(Bcol + (size_t)((t + 1) * BK + kk) * Nn);
                }
            }
#pragma unroll
            for (int kk = 0; kk < BK; ++kk) {
                float a[TM], bb[8];
#pragma unroll
                for (int v = 0; v < TM / 4; ++v) {
                    float4 a4 = *reinterpret_cast<const float4*>(&As[cur][kk][tm * TM + 4 * v]);
                    a[4 * v] = a4.x; a[4 * v + 1] = a4.y;
                    a[4 * v + 2] = a4.z; a[4 * v + 3] = a4.w;
                }
                float4 b0v = *reinterpret_cast<const float4*>(&Bs[cur][kk][tn * 8]);
                float4 b1v = *reinterpret_cast<const float4*>(&Bs[cur][kk][tn * 8 + 4]);
                bb[0] = b0v.x; bb[1] = b0v.y; bb[2] = b0v.z; bb[3] = b0v.w;
                bb[4] = b1v.x; bb[5] = b1v.y; bb[6] = b1v.z; bb[7] = b1v.w;
#pragma unroll
                for (int i = 0; i < TM; ++i)
#pragma unroll
                    for (int j = 0; j < 8; ++j)
                        acc[i][j] = fmaf(a[i], bb[j], acc[i][j]);
            }
            if (t + 1 < ntiles) {
                int nxt = cur ^ 1;
#pragma unroll
                for (int i = 0; i < APT; ++i) As[nxt][a_k + i][a_m] = ra[i];
#pragma unroll
                for (int v = 0; v < BQ; ++v)
                    *(float4*)&Bs[nxt][b_k + v * 8][b_c] = rb[v];
            }
            __syncthreads();
        }
    }

    if (!POOL) {
        float* Y = fbufw(ycode, nullptr) + b * bhalf(ycode);
#pragma unroll
        for (int i = 0; i < TM; ++i) {
            int row = rowBase + tm * TM + i;
            float bv = bias[row];
            float* yr = Y + (size_t)row * Nn + colBase + tn * 8;
#pragma unroll
            for (int j = 0; j < 8; ++j) {
                float v = acc[i][j] + bv;
                yr[j] = RELU ? (v > 0.f ? v : 0.f) : v;
            }
        }
    } else {
        long long Q = Nn >> 5;
        float* Y = (ycode < 0) ? yext + (size_t)b * M * Q
                               : fbufw(ycode, nullptr) + b * bhalf(ycode);
#pragma unroll
        for (int i = 0; i < TM; ++i) {
            float m = acc[i][0];
#pragma unroll
            for (int j = 1; j < 8; ++j) m = fmaxf(m, acc[i][j]);
            m = fmaxf(m, __shfl_xor_sync(0xffffffffu, m, 1));
            m = fmaxf(m, __shfl_xor_sync(0xffffffffu, m, 2));
            if ((tn & 3) == 0) {
                int row = rowBase + tm * TM + i;
                float v = m + bias[row];
                long long q = (colBase >> 5) + (tn >> 2);
                Y[(size_t)row * Q + q] = v > 0.f ? v : 0.f;
            }
        }
    }
}

// ---------------- GEMM64: M=64, BN=256, 4x16 thread tile (no pool) ----------
// K % 16 == 0 required. 64 FMA per 5 LDS -> ~2x FMA fraction vs 64x128 tile.
template <bool RELU>
__global__ __launch_bounds__(256, 2)
void k_gemm64(const float* __restrict__ Wt, const float* __restrict__ bias,
              int xcode, int ycode, int K, int ldw, long long Nn, int b0) {
    __shared__ __align__(16) float As[2][16][64];
    __shared__ __align__(16) float Bs[2][16][256];
    int b = blockIdx.z + b0;
    const float* X = fbufc(xcode, nullptr) + b * bhalf(xcode);
    int tid = threadIdx.x;
    int tm = tid >> 4, tn = tid & 15;          // 16x16 threads, tile 4x16
    long long colBase = (long long)blockIdx.x * 256;

    float acc[4][16];
#pragma unroll
    for (int i = 0; i < 4; ++i)
#pragma unroll
        for (int j = 0; j < 16; ++j) acc[i][j] = 0.f;

    const int a_m = tid >> 2;                  // 0..63
    const int a_k = (tid & 3) * 4;             // 0,4,8,12
    const int b_k = tid >> 6;                  // 0..3 (+v*4)
    const int b_c = (tid & 63) * 4;

    const float* Arow = Wt + (size_t)a_m * ldw + a_k;
    const float* Bcol = X + colBase + b_c;

    float ra[4];
    float4 rb[4];
#pragma unroll
    for (int i = 0; i < 4; ++i) As[0][a_k + i][a_m] = Arow[i];
#pragma unroll
    for (int v = 0; v < 4; ++v) {
        int kk = b_k + v * 4;
        *(float4*)&Bs[0][kk][b_c] = *(const float4*)(Bcol + (size_t)kk * Nn);
    }
    __syncthreads();

    const int ntiles = K / 16;
    for (int t = 0; t < ntiles; ++t) {
        int cur = t & 1;
        if (t + 1 < ntiles) {
            const float* An = Arow + (t + 1) * 16;
#pragma unroll
            for (int i = 0; i < 4; ++i) ra[i] = An[i];
#pragma unroll
            for (int v = 0; v < 4; ++v) {
                int kk = b_k + v * 4;
                rb[v] = *(const float4*)(Bcol + (size_t)((t + 1) * 16 + kk) * Nn);
            }
        }
#pragma unroll
        for (int kk = 0; kk < 16; ++kk) {
            float4 a4 = *reinterpret_cast<const float4*>(&As[cur][kk][tm * 4]);
            float a[4] = {a4.x, a4.y, a4.z, a4.w};
            float bb[16];
#pragma unroll
            for (int v = 0; v < 4; ++v) {
                float4 bv = *reinterpret_cast<const float4*>(&Bs[cur][kk][tn * 16 + 4 * v]);
                bb[4 * v] = bv.x; bb[4 * v + 1] = bv.y;
                bb[4 * v + 2] = bv.z; bb[4 * v + 3] = bv.w;
            }
#pragma unroll
            for (int i = 0; i < 4; ++i)
#pragma unroll
                for (int j = 0; j < 16; ++j)
                    acc[i][j] = fmaf(a[i], bb[j], acc[i][j]);
        }
        if (t + 1 < ntiles) {
            int nxt = cur ^ 1;
#pragma unroll
            for (int i = 0; i < 4; ++i) As[nxt][a_k + i][a_m] = ra[i];
#pragma unroll
            for (int v = 0; v < 4; ++v)
                *(float4*)&Bs[nxt][b_k + v * 4][b_c] = rb[v];
        }
        __syncthreads();
    }

    float* Y = fbufw(ycode, nullptr) + b * bhalf(ycode);
#pragma unroll
    for (int i = 0; i < 4; ++i) {
        int row = tm * 4 + i;
        float bv = bias[row];
        float* yr = Y + (size_t)row * Nn + colBase + tn * 16;
#pragma unroll
        for (int v = 0; v < 4; ++v) {
            float4 o;
            float v0 = acc[i][4 * v + 0] + bv;
            float v1 = acc[i][4 * v + 1] + bv;
            float v2 = acc[i][4 * v + 2] + bv;
            float v3 = acc[i][4 * v + 3] + bv;
            o.x = RELU ? (v0 > 0.f ? v0 : 0.f) : v0;
            o.y = RELU ? (v1 > 0.f ? v1 : 0.f) : v1;
            o.z = RELU ? (v2 > 0.f ? v2 : 0.f) : v2;
            o.w = RELU ? (v3 > 0.f ? v3 : 0.f) : v3;
            *(float4*)(yr + 4 * v) = o;
        }
    }
}

// ---------------- stream/event handles (created at load, before harness) ----
struct HxStreams {
    cudaStream_t s2, s4;
    cudaEvent_t evT, evA, evP, evB1, evB2, evD;
    bool ok;
    HxStreams() {
        ok = cudaStreamCreateWithFlags(&s2, cudaStreamNonBlocking) == cudaSuccess
          && cudaStreamCreateWithFlags(&s4, cudaStreamNonBlocking) == cudaSuccess
          && cudaEventCreateWithFlags(&evT, cudaEventDisableTiming) == cudaSuccess
          && cudaEventCreateWithFlags(&evA, cudaEventDisableTiming) == cudaSuccess
          && cudaEventCreateWithFlags(&evP, cudaEventDisableTiming) == cudaSuccess
          && cudaEventCreateWithFlags(&evB1, cudaEventDisableTiming) == cudaSuccess
          && cudaEventCreateWithFlags(&evB2, cudaEventDisableTiming) == cudaSuccess
          && cudaEventCreateWithFlags(&evD, cudaEventDisableTiming) == cudaSuccess;
    }
};
static HxStreams g_hx;

// ---------------------------------------------------------------------------
extern "C" void kernel_launch(void* const* d_in, const int* in_sizes, int n_in,
                              void* d_out, int out_size) {
    (void)in_sizes; (void)n_in; (void)out_size;
    const float* xyz = (const float*)d_in[0];
    const float* W[4][3]; const float* BV[4][3];
    {
        int p = 1;
        for (int k = 0; k < 4; ++k)
            for (int l = 0; l < 3; ++l) {
                W[k][l]  = (const float*)d_in[p++];
                BV[k][l] = (const float*)d_in[p++];
            }
    }

    static const int   Ns[4]  = {16384, 4096, 1024, 256};
    static const int   CIN[4] = {6, 131, 259, 515};
    static const int   C1[4]  = {64, 128, 256, 512};
    static const int   C2[4]  = {64, 128, 256, 512};
    static const int   C3[4]  = {128, 256, 512, 1024};
    static const float R2[4]  = {(float)(0.1 * 0.1), (float)(0.2 * 0.2),
                                 (float)(0.4 * 0.4), (float)(0.8 * 0.8)};
    static const int supc[4] = {-1, 6, 7, 8};   // support xyz buffer (-1 -> SoA feats0)
    static const int qc[4]   = {6, 7, 8, 9};    // query   xyz buffer
    static const int fic[4]  = {5, 3, 4, 3};    // feats-in buffer
    static const int foc[4]  = {3, 4, 3, -1};   // pooled feats-out

    auto gemm = [&](cudaStream_t st, const float* Wp, const float* bp,
                    int xc, int yc, float* ye, int M, int K, int ldw,
                    long long Nn, bool pool, bool relu, int b0, int zdim) {
        bool guard = (K % 16) != 0;
        if (M >= 128) {
            dim3 g((unsigned)(Nn / 128), M / 128, zdim);
            if (guard) {
                if (pool) k_gemm<128, 16, 8, true,  true,  true ><<<g, 256, 0, st>>>(Wp, bp, xc, yc, ye, M, K, ldw, Nn, b0);
                else if (relu) k_gemm<128, 16, 8, false, true,  true ><<<g, 256, 0, st>>>(Wp, bp, xc, yc, ye, M, K, ldw, Nn, b0);
                else k_gemm<128, 16, 8, false, false, true ><<<g, 256, 0, st>>>(Wp, bp, xc, yc, ye, M, K, ldw, Nn, b0);
            } else {
                if (pool) k_gemm<128, 16, 8, true,  true,  false><<<g, 256, 0, st>>>(Wp, bp, xc, yc, ye, M, K, ldw, Nn, b0);
                else if (relu) k_gemm<128, 16, 8, false, true,  false><<<g, 256, 0, st>>>(Wp, bp, xc, yc, ye, M, K, ldw, Nn, b0);
                else k_gemm<128, 16, 8, false, false, false><<<g, 256, 0, st>>>(Wp, bp, xc, yc, ye, M, K, ldw, Nn, b0);
            }
        } else if (!guard && !pool) {
            // M == 64, K % 16 == 0, no pool: wide-tile path
            dim3 g((unsigned)(Nn / 256), 1, zdim);
            if (relu) k_gemm64<true ><<<g, 256, 0, st>>>(Wp, bp, xc, yc, K, ldw, Nn, b0);
            else      k_gemm64<false><<<g, 256, 0, st>>>(Wp, bp, xc, yc, K, ldw, Nn, b0);
        } else {
            dim3 g((unsigned)(Nn / 128), M / 64, zdim);
            if (guard) {
                if (pool) k_gemm<64, 16, 4, true,  true,  true ><<<g, 256, 0, st>>>(Wp, bp, xc, yc, ye, M, K, ldw, Nn, b0);
                else if (relu) k_gemm<64, 16, 4, false, true,  true ><<<g, 256, 0, st>>>(Wp, bp, xc, yc, ye, M, K, ldw, Nn, b0);
                else k_gemm<64, 16, 4, false, false, true ><<<g, 256, 0, st>>>(Wp, bp, xc, yc, ye, M, K, ldw, Nn, b0);
            } else {
                if (pool) k_gemm<64, 16, 4, true,  true,  false><<<g, 256, 0, st>>>(Wp, bp, xc, yc, ye, M, K, ldw, Nn, b0);
                else k_gemm<64, 16, 4, false, false, false><<<g, 256, 0, st>>>(Wp, bp, xc, yc, ye, M, K, ldw, Nn, b0);
            }
        }
    };

    auto ball = [&](cudaStream_t st, int k, int b) {
        int N = Ns[k], Q = N / 4;
        size_t smem = (size_t)C1[k] * 3 * 4 + 8 * 32 * 4;
        k_ball_l1<<<Q / 8, 256, smem, st>>>(
            xyz, supc[k], qc[k], W[k][0], CIN[k], C1[k], Q, N, R2[k], b);
    };

    // per-batch stage chain (stages 0..3); P0 must already be done.
    auto chain = [&](cudaStream_t sb, int b, bool ov) {
        for (int k = 0; k < 4; ++k) {
            int N = Ns[k], Q = N / 4;
            long long Nn = (long long)Q * 32;
            if (k >= 1)
                gemm(sb, W[k][0] + 3, BV[k][0], fic[k], 0, nullptr,
                     C1[k], CIN[k] - 3, CIN[k], (long long)N, false, false, b, 1);
            if (k == 1 && ov) cudaStreamWaitEvent(sb, g_hx.evB1, 0);  // q1 ready
            if (k == 2 && ov) cudaStreamWaitEvent(sb, g_hx.evB2, 0);  // q2/q3 ready
            ball(sb, k, b);
            gemm(sb, W[k][1], BV[k][1], 1, 2, nullptr,
                 C2[k], C1[k], C1[k], Nn, false, true, b, 1);
            gemm(sb, W[k][2], BV[k][2], 2, foc[k], (float*)d_out,
                 C3[k], C2[k], C2[k], Nn, true, true, b, 1);
        }
    };

    const bool ov = g_hx.ok;

    if (ov) {
        cudaStream_t s2 = g_hx.s2, s4 = g_hx.s4;
        // s0: transpose -> evT -> FPS0 (alone on the chip) -> evA
        k_transpose<<<(2 * 16384 + 255) / 256, 256>>>(xyz);
        cudaEventRecord(g_hx.evT, 0);
        k_fps_cl<<<16, 512>>>(xyz, 16384, 4096);
        cudaEventRecord(g_hx.evA, 0);
        // s2: P0 (both batches, tiny) under FPS0; then stage-1 FPS -> evB1,
        // stages 2-3 -> evB2 (single-CTA kernels; cluster FPS only for stage 0)
        cudaStreamWaitEvent(s2, g_hx.evT, 0);
        gemm(s2, W[0][0] + 3, BV[0][0], fic[0], 0, nullptr,
             C1[0], CIN[0] - 3, CIN[0], 16384LL, false, false, 0, 2);
        cudaEventRecord(g_hx.evP, s2);
        cudaStreamWaitEvent(s2, g_hx.evA, 0);
        k_fps_s1<<<2, 1024, 0, s2>>>();
        cudaEventRecord(g_hx.evB1, s2);
        k_fps_s23<<<2, 1024, 0, s2>>>();
        cudaEventRecord(g_hx.evB2, s2);
        // batch 0 chain on s0 (after fps_cl in program order; needs P0)
        cudaStreamWaitEvent(0, g_hx.evP, 0);
        // batch 1 chain on s4 (fork via in-graph events evA + evP)
        cudaStreamWaitEvent(s4, g_hx.evA, 0);
        cudaStreamWaitEvent(s4, g_hx.evP, 0);
        chain(s4, 1, true);
        cudaEventRecord(g_hx.evD, s4);
        chain(0, 0, true);
        cudaStreamWaitEvent(0, g_hx.evD, 0);             // join batch-1 chain
    } else {
        // sequential fallback
        k_transpose<<<(2 * 16384 + 255) / 256, 256>>>(xyz);
        k_fps_cl<<<16, 512>>>(xyz, 16384, 4096);
        k_fps_s1<<<2, 1024>>>();
        k_fps_s23<<<2, 1024>>>();
        gemm(0, W[0][0] + 3, BV[0][0], fic[0], 0, nullptr,
             C1[0], CIN[0] - 3, CIN[0], 16384LL, false, false, 0, 2);
        for (int k = 0; k < 4; ++k) {
            int N = Ns[k], Q = N / 4;
            long long Nn = (long long)Q * 32;
            if (k >= 1)
                gemm(0, W[k][0] + 3, BV[k][0], fic[k], 0, nullptr,
                     C1[k], CIN[k] - 3, CIN[k], (long long)N, false, false, 0, 2);
            ball(0, k, 0);
            ball(0, k, 1);
            gemm(0, W[k][1], BV[k][1], 1, 2, nullptr,
                 C2[k], C1[k], C1[k], Nn, false, true, 0, 2);
            gemm(0, W[k][2], BV[k][2], 2, foc[k], (float*)d_out,
                 C3[k], C2[k], C2[k], Nn, true, true, 0, 2);
        }
    }
}